// round 1
// baseline (speedup 1.0000x reference)
#include <cuda_runtime.h>
#include <cuda_bf16.h>
#include <cstdint>

// ----------------------------------------------------------------------------
// DiscreteKeyValueBottleneck: argmin_k ||x - e_k||^2 then gather values[k].
// Round 0: fused fp32 SIMT GEMM+argmin baseline.
//   dist(b,n,k) = x_sq - 2 x.e_k + e_sq_k ; argmin over k == argmin(e_sq_k - 2 x.e_k)
// ----------------------------------------------------------------------------

#define KDIM   512
#define MAX_CODES 8192
#define MAX_TOK   16384

#define BM 64      // x rows per block (resident in smem)
#define BN 128     // codes per N-tile
#define BK 32      // k-chunk for streamed codebook tile
#define TM 4       // per-thread rows
#define TN 8       // per-thread cols
#define XPAD 68    // padded row-length for transposed x tile (bank-conflict relief)
#define EPAD 132   // padded row-length for transposed e tile
#define NTHREADS 256

__device__ float d_esq[MAX_CODES];
__device__ int   d_bestidx[MAX_TOK];

// ---------------------------------------------------------------------------
// Kernel 1: e_sq[k] = sum_d codebook[k][d]^2   (one warp per code)
// ---------------------------------------------------------------------------
__global__ void esq_kernel(const float* __restrict__ cb, int ncodes) {
    int warp = (blockIdx.x * blockDim.x + threadIdx.x) >> 5;
    int lane = threadIdx.x & 31;
    if (warp >= ncodes) return;
    const float4* row = reinterpret_cast<const float4*>(cb + (size_t)warp * KDIM);
    float s = 0.f;
    #pragma unroll
    for (int i = 0; i < KDIM / 4 / 32; ++i) {
        float4 v = row[lane + i * 32];
        s += v.x * v.x + v.y * v.y + v.z * v.z + v.w * v.w;
    }
    #pragma unroll
    for (int o = 16; o > 0; o >>= 1) s += __shfl_xor_sync(0xffffffffu, s, o);
    if (lane == 0) d_esq[warp] = s;
}

// ---------------------------------------------------------------------------
// Kernel 2: fused GEMM + argmin.
// Each block: 64 x-rows resident in smem (transposed), loops over all codes
// in 128-wide tiles, k streamed in 32-chunks. 16x16 threads, 4x8 micro-tile.
// ---------------------------------------------------------------------------
extern __shared__ float smem[];

__global__ __launch_bounds__(NTHREADS, 1)
void argmin_kernel(const float* __restrict__ x,
                   const float* __restrict__ cb,
                   int ncodes) {
    float* sX = smem;                         // [KDIM][XPAD]  transposed x tile
    float* sE = sX + KDIM * XPAD;             // [BK][EPAD]    transposed e chunk
    float* sRedD = sE + BK * EPAD;            // [BM][16]
    int*   sRedI = (int*)(sRedD + BM * 16);   // [BM][16]

    const int tid = threadIdx.x;
    const int tx = tid & 15;        // code-tile column group
    const int ty = tid >> 4;        // row group
    const int row0 = blockIdx.x * BM;

    // ---- load x tile (64 x 512) transposed into smem (one time) ----
    // 8192 float4s, 32 per thread.
    #pragma unroll
    for (int it = 0; it < (BM * KDIM / 4) / NTHREADS; ++it) {
        int f = tid + it * NTHREADS;
        int r  = f >> 7;            // 128 float4 per row
        int kq = f & 127;
        float4 v = *reinterpret_cast<const float4*>(
            x + (size_t)(row0 + r) * KDIM + kq * 4);
        int k = kq * 4;
        sX[(k + 0) * XPAD + r] = v.x;
        sX[(k + 1) * XPAD + r] = v.y;
        sX[(k + 2) * XPAD + r] = v.z;
        sX[(k + 3) * XPAD + r] = v.w;
    }

    float bestD[TM];
    int   bestI[TM];
    #pragma unroll
    for (int i = 0; i < TM; ++i) { bestD[i] = 3.4e38f; bestI[i] = 0; }

    for (int nt = 0; nt < ncodes; nt += BN) {
        float acc[TM][TN];
        #pragma unroll
        for (int i = 0; i < TM; ++i)
            #pragma unroll
            for (int j = 0; j < TN; ++j) acc[i][j] = 0.f;

        for (int kc = 0; kc < KDIM; kc += BK) {
            __syncthreads();   // prior compute (or x-load) done before refill
            // load e chunk: BN codes x BK k, transposed. 1024 float4s, 4/thread.
            #pragma unroll
            for (int it = 0; it < (BN * BK / 4) / NTHREADS; ++it) {
                int f = tid + it * NTHREADS;
                int c  = f >> 3;      // BK/4 = 8 float4 per code
                int kq = f & 7;
                float4 v = *reinterpret_cast<const float4*>(
                    cb + (size_t)(nt + c) * KDIM + kc + kq * 4);
                int k = kq * 4;
                sE[(k + 0) * EPAD + c] = v.x;
                sE[(k + 1) * EPAD + c] = v.y;
                sE[(k + 2) * EPAD + c] = v.z;
                sE[(k + 3) * EPAD + c] = v.w;
            }
            __syncthreads();

            #pragma unroll
            for (int k = 0; k < BK; ++k) {
                const float4 av  = *reinterpret_cast<const float4*>(
                    &sX[(kc + k) * XPAD + ty * TM]);
                const float4 bv0 = *reinterpret_cast<const float4*>(
                    &sE[k * EPAD + tx * TN]);
                const float4 bv1 = *reinterpret_cast<const float4*>(
                    &sE[k * EPAD + tx * TN + 4]);
                float a[TM] = {av.x, av.y, av.z, av.w};
                float b[TN] = {bv0.x, bv0.y, bv0.z, bv0.w,
                               bv1.x, bv1.y, bv1.z, bv1.w};
                #pragma unroll
                for (int i = 0; i < TM; ++i)
                    #pragma unroll
                    for (int j = 0; j < TN; ++j)
                        acc[i][j] += a[i] * b[j];
            }
        }

        // score this code tile: dist = e_sq - 2*dot (x_sq constant per row)
        #pragma unroll
        for (int j = 0; j < TN; ++j) {
            int code = nt + tx * TN + j;
            float es = d_esq[code];
            #pragma unroll
            for (int i = 0; i < TM; ++i) {
                float d = fmaf(-2.f, acc[i][j], es);
                if (d < bestD[i]) { bestD[i] = d; bestI[i] = code; }
            }
        }
    }

    // ---- cross-thread (tx) argmin reduction per row ----
    __syncthreads();
    #pragma unroll
    for (int i = 0; i < TM; ++i) {
        int r = ty * TM + i;
        sRedD[r * 16 + tx] = bestD[i];
        sRedI[r * 16 + tx] = bestI[i];
    }
    __syncthreads();
    if (tid < BM) {
        float bd = sRedD[tid * 16];
        int   bi = sRedI[tid * 16];
        #pragma unroll
        for (int t = 1; t < 16; ++t) {
            float dd = sRedD[tid * 16 + t];
            int   ii = sRedI[tid * 16 + t];
            if (dd < bd || (dd == bd && ii < bi)) { bd = dd; bi = ii; }
        }
        d_bestidx[row0 + tid] = bi;
    }
}

// ---------------------------------------------------------------------------
// Kernel 3: gather values[bestidx[row]] -> out[row]
// ---------------------------------------------------------------------------
__global__ void gather_kernel(const float* __restrict__ values,
                              float* __restrict__ out) {
    int row = blockIdx.x;
    int idx = d_bestidx[row];
    const float4* src = reinterpret_cast<const float4*>(values + (size_t)idx * KDIM);
    float4* dst = reinterpret_cast<float4*>(out + (size_t)row * KDIM);
    #pragma unroll
    for (int it = 0; it < (KDIM / 4) / 128; ++it)
        dst[threadIdx.x + it * 128] = src[threadIdx.x + it * 128];
}

// ---------------------------------------------------------------------------
extern "C" void kernel_launch(void* const* d_in, const int* in_sizes, int n_in,
                              void* d_out, int out_size) {
    const float* x      = (const float*)d_in[0];   // [8,2048,512] -> 16384 x 512
    const float* cb     = (const float*)d_in[1];   // [8192,512]
    const float* values = (const float*)d_in[2];   // [8192,512]
    float* out = (float*)d_out;

    const int ntok   = in_sizes[0] / KDIM;   // 16384
    const int ncodes = in_sizes[1] / KDIM;   // 8192

    const size_t smem_bytes =
        (size_t)(KDIM * XPAD + BK * EPAD + BM * 16) * sizeof(float) +
        (size_t)(BM * 16) * sizeof(int);     // 164,352 B
    cudaFuncSetAttribute(argmin_kernel,
                         cudaFuncAttributeMaxDynamicSharedMemorySize,
                         (int)smem_bytes);

    esq_kernel<<<(ncodes + 7) / 8, 256>>>(cb, ncodes);
    argmin_kernel<<<ntok / BM, NTHREADS, smem_bytes>>>(x, cb, ncodes);
    gather_kernel<<<ntok, 128>>>(values, out);
}

// round 4
// speedup vs baseline: 9.1056x; 9.1056x over previous
#include <cuda_runtime.h>
#include <cuda_bf16.h>
#include <cstdint>

// ============================================================================
// DiscreteKeyValueBottleneck — bf16 mma.sync GEMM + top-3 candidates + exact
// fp32 fixup + fused gather.  (tcgen05 unavailable: PTX target is compute_100)
// ============================================================================

#define KDIM     512
#define NCODES   8192
#define NTOK     16384
#define BM       128                 // rows / CTA
#define BN       64                  // codes / tile
#define BKC      64                  // k per chunk
#define NS       4                   // cp.async stages
#define KCHUNKS  (KDIM / BKC)        // 8
#define NTILES   (NCODES / BN)       // 128
#define NCHUNKS  (NTILES * KCHUNKS)  // 1024
#define NTHREADS 256

#define XS_BYTES (BM * KDIM * 2)     // 131072
#define ST_BYTES (BN * BKC * 2)      // 8192
#define SMEM_TOTAL (XS_BYTES + NS * ST_BYTES)  // 163840

__device__ __nv_bfloat16 g_xh[NTOK * KDIM];
__device__ __nv_bfloat16 g_eh[NCODES * KDIM];
__device__ float d_esq[NCODES];
__device__ int   g_cand[NTOK * 3];

// ---------------------------------------------------------------------------
__device__ __forceinline__ uint32_t smem_u32(const void* p) {
    uint32_t a;
    asm("{ .reg .u64 t; cvta.to.shared.u64 t, %1; cvt.u32.u64 %0, t; }"
        : "=r"(a) : "l"(p));
    return a;
}
__device__ __forceinline__ void cp16(uint32_t dst, const void* src) {
    asm volatile("cp.async.cg.shared.global [%0], [%1], 16;"
                 :: "r"(dst), "l"(src) : "memory");
}
#define CP_COMMIT() asm volatile("cp.async.commit_group;" ::: "memory")

__device__ __forceinline__ void ldsm4(uint32_t* r, uint32_t addr) {
    asm volatile("ldmatrix.sync.aligned.m8n8.x4.shared.b16 {%0,%1,%2,%3}, [%4];"
                 : "=r"(r[0]), "=r"(r[1]), "=r"(r[2]), "=r"(r[3]) : "r"(addr));
}
__device__ __forceinline__ void mma16816(float* d, const uint32_t* a,
                                         const uint32_t* b) {
    asm volatile(
        "mma.sync.aligned.m16n8k16.row.col.f32.bf16.bf16.f32 "
        "{%0,%1,%2,%3}, {%4,%5,%6,%7}, {%8,%9}, {%0,%1,%2,%3};"
        : "+f"(d[0]), "+f"(d[1]), "+f"(d[2]), "+f"(d[3])
        : "r"(a[0]), "r"(a[1]), "r"(a[2]), "r"(a[3]), "r"(b[0]), "r"(b[1]));
}

// ---------------------------------------------------------------------------
// Pre-pass kernels
// ---------------------------------------------------------------------------
__global__ void esq_kernel(const float* __restrict__ cb) {
    int warp = (blockIdx.x * blockDim.x + threadIdx.x) >> 5;
    int lane = threadIdx.x & 31;
    if (warp >= NCODES) return;
    const float4* row = reinterpret_cast<const float4*>(cb + (size_t)warp * KDIM);
    float s = 0.f;
    #pragma unroll
    for (int i = 0; i < KDIM / 4 / 32; ++i) {
        float4 v = row[lane + i * 32];
        s += v.x * v.x + v.y * v.y + v.z * v.z + v.w * v.w;
    }
    #pragma unroll
    for (int o = 16; o > 0; o >>= 1) s += __shfl_xor_sync(0xffffffffu, s, o);
    if (lane == 0) d_esq[warp] = s;
}

__global__ void conv_kernel(const float* __restrict__ src, int n4, int which) {
    int i = blockIdx.x * blockDim.x + threadIdx.x;
    if (i >= n4) return;
    __nv_bfloat16* dst = which ? g_eh : g_xh;
    float4 v = reinterpret_cast<const float4*>(src)[i];
    __nv_bfloat16 h[4] = {__float2bfloat16(v.x), __float2bfloat16(v.y),
                          __float2bfloat16(v.z), __float2bfloat16(v.w)};
    reinterpret_cast<uint2*>(dst)[i] = *reinterpret_cast<uint2*>(h);
}

// ---------------------------------------------------------------------------
// Main kernel
// ---------------------------------------------------------------------------
extern __shared__ __align__(1024) char smem[];

__device__ __forceinline__ void load_chunk(uint32_t st_u, int g, int tid) {
    const int t = g >> 3, kc = g & 7, s = g & (NS - 1);
    const __nv_bfloat16* src = g_eh + (size_t)(t * BN) * KDIM + kc * BKC;
    const uint32_t dst = st_u + s * ST_BYTES;
    #pragma unroll
    for (int i = 0; i < 2; ++i) {
        int idx = tid + i * NTHREADS;     // 512 16B segs
        int c = idx >> 3, sg = idx & 7;
        uint32_t kb = sg * 16;
        cp16(dst + c * 128 + (kb ^ ((c & 7) << 4)),
             src + (size_t)c * KDIM + sg * 8);
    }
}

#define INS3(rs, d, i)                                                   \
    do {                                                                 \
        if ((d) < td2[rs]) {                                             \
            td2[rs] = (d); ti2[rs] = (i);                                \
            if (td2[rs] < td1[rs]) {                                     \
                float _t = td1[rs]; td1[rs] = td2[rs]; td2[rs] = _t;     \
                int _u = ti1[rs]; ti1[rs] = ti2[rs]; ti2[rs] = _u;       \
                if (td1[rs] < td0[rs]) {                                 \
                    _t = td0[rs]; td0[rs] = td1[rs]; td1[rs] = _t;       \
                    _u = ti0[rs]; ti0[rs] = ti1[rs]; ti1[rs] = _u;       \
                }                                                        \
            }                                                            \
        }                                                                \
    } while (0)

__global__ __launch_bounds__(NTHREADS, 1) void vq_main() {
    const int tid = threadIdx.x, lane = tid & 31, wid = tid >> 5;
    const int row0 = blockIdx.x * BM;
    const uint32_t xs_u = smem_u32(smem);
    const uint32_t st_u = xs_u + XS_BYTES;

    // ---- resident x tile: 128 x 512 bf16, swizzled ----
    #pragma unroll 4
    for (int i = 0; i < (BM * KDIM / 8) / NTHREADS; ++i) {  // 32
        int idx = tid + i * NTHREADS;
        int r = idx >> 6, sg = idx & 63;
        uint32_t kb = sg * 16;
        cp16(xs_u + r * 1024 + (kb ^ ((r & 7) << 4)),
             g_xh + (size_t)(row0 + r) * KDIM + sg * 8);
    }
    CP_COMMIT();
    #pragma unroll
    for (int g = 0; g < NS - 1; ++g) { load_chunk(st_u, g, tid); CP_COMMIT(); }

    const int rowg = wid >> 1, colg = wid & 1;
    const int mr = rowg * 32, nc = colg * 32;

    float td0[4], td1[4], td2[4];
    int   ti0[4], ti1[4], ti2[4];
    #pragma unroll
    for (int i = 0; i < 4; ++i) {
        td0[i] = td1[i] = td2[i] = 3.4e38f;
        ti0[i] = ti1[i] = ti2[i] = 0;
    }

    float acc[2][4][4];

    #pragma unroll 1
    for (int g = 0; g < NCHUNKS; ++g) {
        asm volatile("cp.async.wait_group %0;" :: "n"(NS - 2));
        __syncthreads();
        if (g + NS - 1 < NCHUNKS) load_chunk(st_u, g + NS - 1, tid);
        CP_COMMIT();

        const int kc = g & 7;
        if (kc == 0) {
            #pragma unroll
            for (int rg = 0; rg < 2; ++rg)
                #pragma unroll
                for (int nf = 0; nf < 4; ++nf)
                    #pragma unroll
                    for (int q = 0; q < 4; ++q) acc[rg][nf][q] = 0.f;
        }

        const uint32_t sbase = st_u + (g & (NS - 1)) * ST_BYTES;
        #pragma unroll
        for (int ks = 0; ks < 4; ++ks) {
            uint32_t a[2][4], b[2][4];
            #pragma unroll
            for (int rg = 0; rg < 2; ++rg) {
                int r = mr + rg * 16 + (lane & 15);
                uint32_t kb = kc * 128 +
                    ((ks * 32 + ((lane >> 4) * 16)) ^ ((r & 7) << 4));
                ldsm4(a[rg], xs_u + r * 1024 + kb);
            }
            #pragma unroll
            for (int p = 0; p < 2; ++p) {
                int c = nc + p * 16 + (lane & 7) + ((lane >> 4) & 1) * 8;
                uint32_t kb = (ks * 32 + (((lane >> 3) & 1) * 16)) ^ ((c & 7) << 4);
                ldsm4(b[p], sbase + c * 128 + kb);
            }
            #pragma unroll
            for (int rg = 0; rg < 2; ++rg)
                #pragma unroll
                for (int p = 0; p < 2; ++p)
                    #pragma unroll
                    for (int q = 0; q < 2; ++q)
                        mma16816(acc[rg][p * 2 + q], a[rg], b[p] + q * 2);
        }

        if (kc == 7) {
            const int code_base = (g >> 3) * BN + nc + (lane & 3) * 2;
            #pragma unroll
            for (int rg = 0; rg < 2; ++rg) {
                #pragma unroll
                for (int nf = 0; nf < 4; ++nf) {
                    const int cg0 = code_base + nf * 8;
                    const float e0 = __ldg(&d_esq[cg0]);
                    const float e1 = __ldg(&d_esq[cg0 + 1]);
                    float d;
                    d = fmaf(-2.f, acc[rg][nf][0], e0); INS3(rg * 2, d, cg0);
                    d = fmaf(-2.f, acc[rg][nf][1], e1); INS3(rg * 2, d, cg0 + 1);
                    d = fmaf(-2.f, acc[rg][nf][2], e0); INS3(rg * 2 + 1, d, cg0);
                    d = fmaf(-2.f, acc[rg][nf][3], e1); INS3(rg * 2 + 1, d, cg0 + 1);
                }
            }
        }
    }

    // ---- per-row merge of 24 candidates -> global top-3 ----
    __syncthreads();
    float* md = reinterpret_cast<float*>(smem + XS_BYTES);          // [128][8][3]
    int*   mi = reinterpret_cast<int*>(smem + XS_BYTES + 128 * 24 * 4);
    const int cid = colg * 4 + (lane & 3);
    #pragma unroll
    for (int rs = 0; rs < 4; ++rs) {
        int r = mr + (rs >> 1) * 16 + (rs & 1) * 8 + (lane >> 2);
        int o = (r * 8 + cid) * 3;
        md[o] = td0[rs]; md[o + 1] = td1[rs]; md[o + 2] = td2[rs];
        mi[o] = ti0[rs]; mi[o + 1] = ti1[rs]; mi[o + 2] = ti2[rs];
    }
    __syncthreads();
    if (tid < BM) {
        float b0 = 3.4e38f, b1 = 3.4e38f, b2 = 3.4e38f;
        int i0 = 0, i1 = 0, i2 = 0;
        #pragma unroll 4
        for (int e = 0; e < 24; ++e) {
            float d = md[tid * 24 + e];
            int ii = mi[tid * 24 + e];
            if (d < b2) {
                b2 = d; i2 = ii;
                if (b2 < b1) {
                    float t = b1; b1 = b2; b2 = t;
                    int u = i1; i1 = i2; i2 = u;
                    if (b1 < b0) {
                        t = b0; b0 = b1; b1 = t;
                        u = i0; i0 = i1; i1 = u;
                    }
                }
            }
        }
        int r = row0 + tid;
        g_cand[r * 3 + 0] = i0;
        g_cand[r * 3 + 1] = i1;
        g_cand[r * 3 + 2] = i2;
    }
}

// ---------------------------------------------------------------------------
// Fixup (exact fp32 rescore of 3 candidates) fused with gather.
// ---------------------------------------------------------------------------
__global__ void fixup_gather(const float* __restrict__ x,
                             const float* __restrict__ cb,
                             const float* __restrict__ values,
                             float* __restrict__ out) {
    const int row = (blockIdx.x * blockDim.x + threadIdx.x) >> 5;
    const int lane = threadIdx.x & 31;
    if (row >= NTOK) return;

    float4 xv[4];
    const float4* xr = reinterpret_cast<const float4*>(x + (size_t)row * KDIM);
    #pragma unroll
    for (int j = 0; j < 4; ++j) xv[j] = xr[lane + j * 32];

    float bd = 3.4e38f;
    int bi = NCODES;
    #pragma unroll
    for (int c = 0; c < 3; ++c) {
        int idx = g_cand[row * 3 + c];
        const float4* er = reinterpret_cast<const float4*>(cb + (size_t)idx * KDIM);
        float s = 0.f;
        #pragma unroll
        for (int j = 0; j < 4; ++j) {
            float4 e = er[lane + j * 32];
            s += xv[j].x * e.x + xv[j].y * e.y + xv[j].z * e.z + xv[j].w * e.w;
        }
        #pragma unroll
        for (int o = 16; o > 0; o >>= 1) s += __shfl_xor_sync(0xffffffffu, s, o);
        float d = fmaf(-2.f, s, d_esq[idx]);
        if (d < bd || (d == bd && idx < bi)) { bd = d; bi = idx; }
    }

    const float4* vr = reinterpret_cast<const float4*>(values + (size_t)bi * KDIM);
    float4* orow = reinterpret_cast<float4*>(out + (size_t)row * KDIM);
    #pragma unroll
    for (int j = 0; j < 4; ++j) orow[lane + j * 32] = vr[lane + j * 32];
}

// ---------------------------------------------------------------------------
extern "C" void kernel_launch(void* const* d_in, const int* in_sizes, int n_in,
                              void* d_out, int out_size) {
    const float* x      = (const float*)d_in[0];   // [16384, 512]
    const float* cb     = (const float*)d_in[1];   // [8192, 512]
    const float* values = (const float*)d_in[2];   // [8192, 512]
    float* out = (float*)d_out;

    cudaFuncSetAttribute(vq_main,
                         cudaFuncAttributeMaxDynamicSharedMemorySize, SMEM_TOTAL);

    esq_kernel<<<NCODES / 8, 256>>>(cb);
    conv_kernel<<<(NTOK * KDIM / 4) / 256, 256>>>(x, NTOK * KDIM / 4, 0);
    conv_kernel<<<(NCODES * KDIM / 4) / 256, 256>>>(cb, NCODES * KDIM / 4, 1);
    vq_main<<<NTOK / BM, NTHREADS, SMEM_TOTAL>>>();
    fixup_gather<<<(NTOK * 32) / 256, 256>>>(x, cb, values, out);
}

// round 6
// speedup vs baseline: 9.7234x; 1.0678x over previous
#include <cuda_runtime.h>
#include <cuda_bf16.h>
#include <cstdint>

// ============================================================================
// DiscreteKeyValueBottleneck — bf16 mma.sync GEMM (32x64 warp tile) + top-3
// candidates + exact fp32 fixup + fused gather.
// ============================================================================

#define KDIM     512
#define NCODES   8192
#define NTOK     16384
#define BM       128                 // rows / CTA
#define BN       128                 // codes / tile
#define BKC      64                  // k per chunk
#define NS       4                   // cp.async stages
#define KCHUNKS  (KDIM / BKC)        // 8
#define NTILES   (NCODES / BN)       // 64
#define NCHUNKS  (NTILES * KCHUNKS)  // 512
#define NTHREADS 256

#define XS_BYTES (BM * KDIM * 2)     // 131072
#define ST_BYTES (BN * BKC * 2)      // 16384
#define SMEM_TOTAL (XS_BYTES + NS * ST_BYTES)  // 196608

__device__ __nv_bfloat16 g_xh[NTOK * KDIM];
__device__ __nv_bfloat16 g_eh[NCODES * KDIM];
__device__ float d_esq[NCODES];
__device__ int   g_cand[NTOK * 3];

// ---------------------------------------------------------------------------
__device__ __forceinline__ uint32_t smem_u32(const void* p) {
    uint32_t a;
    asm("{ .reg .u64 t; cvta.to.shared.u64 t, %1; cvt.u32.u64 %0, t; }"
        : "=r"(a) : "l"(p));
    return a;
}
__device__ __forceinline__ void cp16(uint32_t dst, const void* src) {
    asm volatile("cp.async.cg.shared.global [%0], [%1], 16;"
                 :: "r"(dst), "l"(src) : "memory");
}
#define CP_COMMIT() asm volatile("cp.async.commit_group;" ::: "memory")

__device__ __forceinline__ void ldsm4(uint32_t* r, uint32_t addr) {
    asm volatile("ldmatrix.sync.aligned.m8n8.x4.shared.b16 {%0,%1,%2,%3}, [%4];"
                 : "=r"(r[0]), "=r"(r[1]), "=r"(r[2]), "=r"(r[3]) : "r"(addr));
}
__device__ __forceinline__ void mma16816(float* d, const uint32_t* a,
                                         const uint32_t* b) {
    asm volatile(
        "mma.sync.aligned.m16n8k16.row.col.f32.bf16.bf16.f32 "
        "{%0,%1,%2,%3}, {%4,%5,%6,%7}, {%8,%9}, {%0,%1,%2,%3};"
        : "+f"(d[0]), "+f"(d[1]), "+f"(d[2]), "+f"(d[3])
        : "r"(a[0]), "r"(a[1]), "r"(a[2]), "r"(a[3]), "r"(b[0]), "r"(b[1]));
}

// ---------------------------------------------------------------------------
// Pre-pass kernels
// ---------------------------------------------------------------------------
__global__ void esq_kernel(const float* __restrict__ cb) {
    int warp = (blockIdx.x * blockDim.x + threadIdx.x) >> 5;
    int lane = threadIdx.x & 31;
    if (warp >= NCODES) return;
    const float4* row = reinterpret_cast<const float4*>(cb + (size_t)warp * KDIM);
    float s = 0.f;
    #pragma unroll
    for (int i = 0; i < KDIM / 4 / 32; ++i) {
        float4 v = row[lane + i * 32];
        s += v.x * v.x + v.y * v.y + v.z * v.z + v.w * v.w;
    }
    #pragma unroll
    for (int o = 16; o > 0; o >>= 1) s += __shfl_xor_sync(0xffffffffu, s, o);
    if (lane == 0) d_esq[warp] = s;
}

__global__ void conv_kernel(const float* __restrict__ src, int n4, int which) {
    int i = blockIdx.x * blockDim.x + threadIdx.x;
    if (i >= n4) return;
    __nv_bfloat16* dst = which ? g_eh : g_xh;
    float4 v = reinterpret_cast<const float4*>(src)[i];
    __nv_bfloat16 h[4] = {__float2bfloat16(v.x), __float2bfloat16(v.y),
                          __float2bfloat16(v.z), __float2bfloat16(v.w)};
    reinterpret_cast<uint2*>(dst)[i] = *reinterpret_cast<uint2*>(h);
}

// ---------------------------------------------------------------------------
// Main kernel
// ---------------------------------------------------------------------------
extern __shared__ __align__(1024) char smem[];

__device__ __forceinline__ void load_chunk(uint32_t st_u, int g, int tid) {
    const int t = g >> 3, kc = g & 7, s = g & (NS - 1);
    const __nv_bfloat16* src = g_eh + (size_t)(t * BN) * KDIM + kc * BKC;
    const uint32_t dst = st_u + s * ST_BYTES;
    #pragma unroll
    for (int i = 0; i < 4; ++i) {
        int idx = tid + i * NTHREADS;     // 1024 16B segs
        int c = idx >> 3, sg = idx & 7;
        uint32_t kb = sg * 16;
        cp16(dst + c * 128 + (kb ^ ((c & 7) << 4)),
             src + (size_t)c * KDIM + sg * 8);
    }
}

#define INS3(rs, d, i)                                                   \
    do {                                                                 \
        if ((d) < td2[rs]) {                                             \
            td2[rs] = (d); ti2[rs] = (i);                                \
            if (td2[rs] < td1[rs]) {                                     \
                float _t = td1[rs]; td1[rs] = td2[rs]; td2[rs] = _t;     \
                int _u = ti1[rs]; ti1[rs] = ti2[rs]; ti2[rs] = _u;       \
                if (td1[rs] < td0[rs]) {                                 \
                    _t = td0[rs]; td0[rs] = td1[rs]; td1[rs] = _t;       \
                    _u = ti0[rs]; ti0[rs] = ti1[rs]; ti1[rs] = _u;       \
                }                                                        \
            }                                                            \
        }                                                                \
    } while (0)

__global__ __launch_bounds__(NTHREADS, 1) void vq_main() {
    const int tid = threadIdx.x, lane = tid & 31, wid = tid >> 5;
    const int row0 = blockIdx.x * BM;
    const uint32_t xs_u = smem_u32(smem);
    const uint32_t st_u = xs_u + XS_BYTES;

    // ---- resident x tile: 128 x 512 bf16, swizzled ----
    #pragma unroll 4
    for (int i = 0; i < (BM * KDIM / 8) / NTHREADS; ++i) {  // 32
        int idx = tid + i * NTHREADS;
        int r = idx >> 6, sg = idx & 63;
        uint32_t kb = sg * 16;
        cp16(xs_u + r * 1024 + (kb ^ ((r & 7) << 4)),
             g_xh + (size_t)(row0 + r) * KDIM + sg * 8);
    }
    CP_COMMIT();
    #pragma unroll
    for (int g = 0; g < NS - 1; ++g) { load_chunk(st_u, g, tid); CP_COMMIT(); }

    const int rowg = wid >> 1, colg = wid & 1;
    const int mr = rowg * 32, nc = colg * 64;

    float td0[4], td1[4], td2[4];
    int   ti0[4], ti1[4], ti2[4];
    #pragma unroll
    for (int i = 0; i < 4; ++i) {
        td0[i] = td1[i] = td2[i] = 3.4e38f;
        ti0[i] = ti1[i] = ti2[i] = 0;
    }

    float acc[2][8][4];

    #pragma unroll 1
    for (int g = 0; g < NCHUNKS; ++g) {
        asm volatile("cp.async.wait_group %0;" :: "n"(NS - 2));
        __syncthreads();
        if (g + NS - 1 < NCHUNKS) load_chunk(st_u, g + NS - 1, tid);
        CP_COMMIT();

        const int kc = g & 7;
        if (kc == 0) {
            #pragma unroll
            for (int rg = 0; rg < 2; ++rg)
                #pragma unroll
                for (int nf = 0; nf < 8; ++nf)
                    #pragma unroll
                    for (int q = 0; q < 4; ++q) acc[rg][nf][q] = 0.f;
        }

        const uint32_t sbase = st_u + (g & (NS - 1)) * ST_BYTES;
        #pragma unroll
        for (int ks = 0; ks < 4; ++ks) {
            uint32_t a[2][4], b[4][4];
            #pragma unroll
            for (int rg = 0; rg < 2; ++rg) {
                int r = mr + rg * 16 + (lane & 15);
                uint32_t kb = kc * 128 +
                    ((ks * 32 + ((lane >> 4) * 16)) ^ ((r & 7) << 4));
                ldsm4(a[rg], xs_u + r * 1024 + kb);
            }
            #pragma unroll
            for (int p = 0; p < 4; ++p) {
                int c = nc + p * 16 + (lane & 7) + ((lane >> 4) & 1) * 8;
                uint32_t kb = (ks * 32 + (((lane >> 3) & 1) * 16)) ^ ((c & 7) << 4);
                ldsm4(b[p], sbase + c * 128 + kb);
            }
            #pragma unroll
            for (int rg = 0; rg < 2; ++rg)
                #pragma unroll
                for (int p = 0; p < 4; ++p)
                    #pragma unroll
                    for (int q = 0; q < 2; ++q)
                        mma16816(acc[rg][p * 2 + q], a[rg], b[p] + q * 2);
        }

        if (kc == 7) {
            const int code_base = (g >> 3) * BN + nc + (lane & 3) * 2;
            #pragma unroll
            for (int rg = 0; rg < 2; ++rg) {
                #pragma unroll
                for (int nf = 0; nf < 8; ++nf) {
                    const int cg0 = code_base + nf * 8;
                    const float e0 = __ldg(&d_esq[cg0]);
                    const float e1 = __ldg(&d_esq[cg0 + 1]);
                    float d;
                    d = fmaf(-2.f, acc[rg][nf][0], e0); INS3(rg * 2, d, cg0);
                    d = fmaf(-2.f, acc[rg][nf][1], e1); INS3(rg * 2, d, cg0 + 1);
                    d = fmaf(-2.f, acc[rg][nf][2], e0); INS3(rg * 2 + 1, d, cg0);
                    d = fmaf(-2.f, acc[rg][nf][3], e1); INS3(rg * 2 + 1, d, cg0 + 1);
                }
            }
        }
    }

    // ---- per-row merge of 24 candidates -> global top-3 ----
    __syncthreads();
    float* md = reinterpret_cast<float*>(smem + XS_BYTES);          // [128][8][3]
    int*   mi = reinterpret_cast<int*>(smem + XS_BYTES + 128 * 24 * 4);
    const int cid = colg * 4 + (lane & 3);
    #pragma unroll
    for (int rs = 0; rs < 4; ++rs) {
        int r = mr + (rs >> 1) * 16 + (rs & 1) * 8 + (lane >> 2);
        int o = (r * 8 + cid) * 3;
        md[o] = td0[rs]; md[o + 1] = td1[rs]; md[o + 2] = td2[rs];
        mi[o] = ti0[rs]; mi[o + 1] = ti1[rs]; mi[o + 2] = ti2[rs];
    }
    __syncthreads();
    if (tid < BM) {
        float b0 = 3.4e38f, b1 = 3.4e38f, b2 = 3.4e38f;
        int i0 = 0, i1 = 0, i2 = 0;
        #pragma unroll 4
        for (int e = 0; e < 24; ++e) {
            float d = md[tid * 24 + e];
            int ii = mi[tid * 24 + e];
            if (d < b2) {
                b2 = d; i2 = ii;
                if (b2 < b1) {
                    float t = b1; b1 = b2; b2 = t;
                    int u = i1; i1 = i2; i2 = u;
                    if (b1 < b0) {
                        t = b0; b0 = b1; b1 = t;
                        u = i0; i0 = i1; i1 = u;
                    }
                }
            }
        }
        int r = row0 + tid;
        g_cand[r * 3 + 0] = i0;
        g_cand[r * 3 + 1] = i1;
        g_cand[r * 3 + 2] = i2;
    }
}

// ---------------------------------------------------------------------------
// Fixup (exact fp32 rescore of 3 candidates) fused with gather.
// ---------------------------------------------------------------------------
__global__ void fixup_gather(const float* __restrict__ x,
                             const float* __restrict__ cb,
                             const float* __restrict__ values,
                             float* __restrict__ out) {
    const int row = (blockIdx.x * blockDim.x + threadIdx.x) >> 5;
    const int lane = threadIdx.x & 31;
    if (row >= NTOK) return;

    float4 xv[4];
    const float4* xr = reinterpret_cast<const float4*>(x + (size_t)row * KDIM);
    #pragma unroll
    for (int j = 0; j < 4; ++j) xv[j] = xr[lane + j * 32];

    float bd = 3.4e38f;
    int bi = NCODES;
    #pragma unroll
    for (int c = 0; c < 3; ++c) {
        int idx = g_cand[row * 3 + c];
        const float4* er = reinterpret_cast<const float4*>(cb + (size_t)idx * KDIM);
        float s = 0.f;
        #pragma unroll
        for (int j = 0; j < 4; ++j) {
            float4 e = er[lane + j * 32];
            s += xv[j].x * e.x + xv[j].y * e.y + xv[j].z * e.z + xv[j].w * e.w;
        }
        #pragma unroll
        for (int o = 16; o > 0; o >>= 1) s += __shfl_xor_sync(0xffffffffu, s, o);
        float d = fmaf(-2.f, s, d_esq[idx]);
        if (d < bd || (d == bd && idx < bi)) { bd = d; bi = idx; }
    }

    const float4* vr = reinterpret_cast<const float4*>(values + (size_t)bi * KDIM);
    float4* orow = reinterpret_cast<float4*>(out + (size_t)row * KDIM);
    #pragma unroll
    for (int j = 0; j < 4; ++j) orow[lane + j * 32] = vr[lane + j * 32];
}

// ---------------------------------------------------------------------------
extern "C" void kernel_launch(void* const* d_in, const int* in_sizes, int n_in,
                              void* d_out, int out_size) {
    const float* x      = (const float*)d_in[0];   // [16384, 512]
    const float* cb     = (const float*)d_in[1];   // [8192, 512]
    const float* values = (const float*)d_in[2];   // [8192, 512]
    float* out = (float*)d_out;

    cudaFuncSetAttribute(vq_main,
                         cudaFuncAttributeMaxDynamicSharedMemorySize, SMEM_TOTAL);

    esq_kernel<<<NCODES / 8, 256>>>(cb);
    conv_kernel<<<(NTOK * KDIM / 4) / 256, 256>>>(x, NTOK * KDIM / 4, 0);
    conv_kernel<<<(NCODES * KDIM / 4) / 256, 256>>>(cb, NCODES * KDIM / 4, 1);
    vq_main<<<NTOK / BM, NTHREADS, SMEM_TOTAL>>>();
    fixup_gather<<<(NTOK * 32) / 256, 256>>>(x, cb, values, out);
}

// round 8
// speedup vs baseline: 10.4067x; 1.0703x over previous
#include <cuda_runtime.h>
#include <cuda_bf16.h>
#include <cstdint>

// ============================================================================
// DiscreteKeyValueBottleneck — bf16 mma.sync GEMM, 512-thread CTA (4x4 warps,
// 32x32 warp tile), hoisted ldsm addresses, top-3 + exact fp32 fixup + gather.
// ============================================================================

#define KDIM     512
#define NCODES   8192
#define NTOK     16384
#define BM       128                 // rows / CTA
#define BN       128                 // codes / tile
#define BKC      64                  // k per chunk
#define NS       4                   // cp.async stages
#define KCHUNKS  (KDIM / BKC)        // 8
#define NTILES   (NCODES / BN)       // 64
#define NCHUNKS  (NTILES * KCHUNKS)  // 512
#define NTHREADS 512

#define XS_BYTES (BM * KDIM * 2)     // 131072
#define ST_BYTES (BN * BKC * 2)      // 16384
#define SMEM_TOTAL (XS_BYTES + NS * ST_BYTES)  // 196608

__device__ __nv_bfloat16 g_xh[NTOK * KDIM];
__device__ __nv_bfloat16 g_eh[NCODES * KDIM];
__device__ float d_esq[NCODES];
__device__ int   g_cand[NTOK * 3];

// ---------------------------------------------------------------------------
__device__ __forceinline__ uint32_t smem_u32(const void* p) {
    uint32_t a;
    asm("{ .reg .u64 t; cvta.to.shared.u64 t, %1; cvt.u32.u64 %0, t; }"
        : "=r"(a) : "l"(p));
    return a;
}
__device__ __forceinline__ void cp16(uint32_t dst, const void* src) {
    asm volatile("cp.async.cg.shared.global [%0], [%1], 16;"
                 :: "r"(dst), "l"(src) : "memory");
}
#define CP_COMMIT() asm volatile("cp.async.commit_group;" ::: "memory")

__device__ __forceinline__ void ldsm4(uint32_t* r, uint32_t addr) {
    asm volatile("ldmatrix.sync.aligned.m8n8.x4.shared.b16 {%0,%1,%2,%3}, [%4];"
                 : "=r"(r[0]), "=r"(r[1]), "=r"(r[2]), "=r"(r[3]) : "r"(addr));
}
__device__ __forceinline__ void mma16816(float* d, const uint32_t* a,
                                         const uint32_t* b) {
    asm volatile(
        "mma.sync.aligned.m16n8k16.row.col.f32.bf16.bf16.f32 "
        "{%0,%1,%2,%3}, {%4,%5,%6,%7}, {%8,%9}, {%0,%1,%2,%3};"
        : "+f"(d[0]), "+f"(d[1]), "+f"(d[2]), "+f"(d[3])
        : "r"(a[0]), "r"(a[1]), "r"(a[2]), "r"(a[3]), "r"(b[0]), "r"(b[1]));
}

// ---------------------------------------------------------------------------
// Pre-pass kernels
// ---------------------------------------------------------------------------
__global__ void esq_kernel(const float* __restrict__ cb) {
    int warp = (blockIdx.x * blockDim.x + threadIdx.x) >> 5;
    int lane = threadIdx.x & 31;
    if (warp >= NCODES) return;
    const float4* row = reinterpret_cast<const float4*>(cb + (size_t)warp * KDIM);
    float s = 0.f;
    #pragma unroll
    for (int i = 0; i < KDIM / 4 / 32; ++i) {
        float4 v = row[lane + i * 32];
        s += v.x * v.x + v.y * v.y + v.z * v.z + v.w * v.w;
    }
    #pragma unroll
    for (int o = 16; o > 0; o >>= 1) s += __shfl_xor_sync(0xffffffffu, s, o);
    if (lane == 0) d_esq[warp] = s;
}

__global__ void conv_kernel(const float* __restrict__ src, int n4, int which) {
    int i = blockIdx.x * blockDim.x + threadIdx.x;
    if (i >= n4) return;
    __nv_bfloat16* dst = which ? g_eh : g_xh;
    float4 v = reinterpret_cast<const float4*>(src)[i];
    __nv_bfloat16 h[4] = {__float2bfloat16(v.x), __float2bfloat16(v.y),
                          __float2bfloat16(v.z), __float2bfloat16(v.w)};
    reinterpret_cast<uint2*>(dst)[i] = *reinterpret_cast<uint2*>(h);
}

// ---------------------------------------------------------------------------
// Main kernel
// ---------------------------------------------------------------------------
extern __shared__ __align__(1024) char smem[];

__device__ __forceinline__ void load_chunk(uint32_t st_u, int g, int tid) {
    const int t = g >> 3, kc = g & 7, s = g & (NS - 1);
    const __nv_bfloat16* src = g_eh + (size_t)(t * BN) * KDIM + kc * BKC;
    const uint32_t dst = st_u + s * ST_BYTES;
    #pragma unroll
    for (int i = 0; i < 2; ++i) {
        int idx = tid + i * NTHREADS;     // 1024 16B segs
        int c = idx >> 3, sg = idx & 7;
        uint32_t kb = sg * 16;
        cp16(dst + c * 128 + (kb ^ ((c & 7) << 4)),
             src + (size_t)c * KDIM + sg * 8);
    }
}

#define INS3(rs, d, i)                                                   \
    do {                                                                 \
        if ((d) < td2[rs]) {                                             \
            td2[rs] = (d); ti2[rs] = (i);                                \
            if (td2[rs] < td1[rs]) {                                     \
                float _t = td1[rs]; td1[rs] = td2[rs]; td2[rs] = _t;     \
                int _u = ti1[rs]; ti1[rs] = ti2[rs]; ti2[rs] = _u;       \
                if (td1[rs] < td0[rs]) {                                 \
                    _t = td0[rs]; td0[rs] = td1[rs]; td1[rs] = _t;       \
                    _u = ti0[rs]; ti0[rs] = ti1[rs]; ti1[rs] = _u;       \
                }                                                        \
            }                                                            \
        }                                                                \
    } while (0)

__global__ __launch_bounds__(NTHREADS, 1) void vq_main() {
    const int tid = threadIdx.x, lane = tid & 31, wid = tid >> 5;
    const int row0 = blockIdx.x * BM;
    const uint32_t xs_u = smem_u32(smem);
    const uint32_t st_u = xs_u + XS_BYTES;

    // ---- resident x tile: 128 x 512 bf16, swizzled ----
    #pragma unroll 4
    for (int i = 0; i < (BM * KDIM / 8) / NTHREADS; ++i) {  // 16
        int idx = tid + i * NTHREADS;
        int r = idx >> 6, sg = idx & 63;
        uint32_t kb = sg * 16;
        cp16(xs_u + r * 1024 + (kb ^ ((r & 7) << 4)),
             g_xh + (size_t)(row0 + r) * KDIM + sg * 8);
    }
    CP_COMMIT();
    #pragma unroll
    for (int g = 0; g < NS - 1; ++g) { load_chunk(st_u, g, tid); CP_COMMIT(); }

    const int rowg = wid >> 2, colg = wid & 3;
    const int mr = rowg * 32, nc = colg * 32;

    // ---- precompute swizzled ldsm addresses (hot loop: single IADD each) ----
    uint32_t aAddr[4][2], bAddr[4][2];
    #pragma unroll
    for (int ks = 0; ks < 4; ++ks) {
        #pragma unroll
        for (int rg = 0; rg < 2; ++rg) {
            int r = mr + rg * 16 + (lane & 15);
            aAddr[ks][rg] = xs_u + r * 1024 +
                ((ks * 32 + ((lane >> 4) * 16)) ^ ((r & 7) << 4));
        }
        #pragma unroll
        for (int p = 0; p < 2; ++p) {
            int c = nc + p * 16 + (lane & 7) + ((lane >> 4) & 1) * 8;
            bAddr[ks][p] = c * 128 +
                ((ks * 32 + (((lane >> 3) & 1) * 16)) ^ ((c & 7) << 4));
        }
    }

    float td0[4], td1[4], td2[4];
    int   ti0[4], ti1[4], ti2[4];
    #pragma unroll
    for (int i = 0; i < 4; ++i) {
        td0[i] = td1[i] = td2[i] = 3.4e38f;
        ti0[i] = ti1[i] = ti2[i] = 0;
    }

    float acc[2][4][4];

    #pragma unroll 1
    for (int g = 0; g < NCHUNKS; ++g) {
        asm volatile("cp.async.wait_group %0;" :: "n"(NS - 2));
        __syncthreads();
        if (g + NS - 1 < NCHUNKS) load_chunk(st_u, g + NS - 1, tid);
        CP_COMMIT();

        const int kc = g & 7;
        if (kc == 0) {
            #pragma unroll
            for (int rg = 0; rg < 2; ++rg)
                #pragma unroll
                for (int nf = 0; nf < 4; ++nf)
                    #pragma unroll
                    for (int q = 0; q < 4; ++q) acc[rg][nf][q] = 0.f;
        }

        const uint32_t aOff = kc * 128;
        const uint32_t sbase = st_u + (g & (NS - 1)) * ST_BYTES;
        #pragma unroll
        for (int ks = 0; ks < 4; ++ks) {
            uint32_t a[2][4], b[2][4];
            #pragma unroll
            for (int rg = 0; rg < 2; ++rg) ldsm4(a[rg], aAddr[ks][rg] + aOff);
            #pragma unroll
            for (int p = 0; p < 2; ++p)  ldsm4(b[p], sbase + bAddr[ks][p]);
            #pragma unroll
            for (int rg = 0; rg < 2; ++rg)
                #pragma unroll
                for (int p = 0; p < 2; ++p)
                    #pragma unroll
                    for (int q = 0; q < 2; ++q)
                        mma16816(acc[rg][p * 2 + q], a[rg], b[p] + q * 2);
        }

        if (kc == 7) {
            const int code_base = (g >> 3) * BN + nc + (lane & 3) * 2;
            #pragma unroll
            for (int rg = 0; rg < 2; ++rg) {
                #pragma unroll
                for (int nf = 0; nf < 4; ++nf) {
                    const int cg0 = code_base + nf * 8;
                    const float e0 = __ldg(&d_esq[cg0]);
                    const float e1 = __ldg(&d_esq[cg0 + 1]);
                    float d;
                    d = fmaf(-2.f, acc[rg][nf][0], e0); INS3(rg * 2, d, cg0);
                    d = fmaf(-2.f, acc[rg][nf][1], e1); INS3(rg * 2, d, cg0 + 1);
                    d = fmaf(-2.f, acc[rg][nf][2], e0); INS3(rg * 2 + 1, d, cg0);
                    d = fmaf(-2.f, acc[rg][nf][3], e1); INS3(rg * 2 + 1, d, cg0 + 1);
                }
            }
        }
    }

    // ---- per-row merge of 48 candidates -> global top-3 ----
    __syncthreads();
    float* md = reinterpret_cast<float*>(smem + XS_BYTES);          // [128][16][3]
    int*   mi = reinterpret_cast<int*>(smem + XS_BYTES + 128 * 48 * 4);
    const int cid = colg * 4 + (lane & 3);
    #pragma unroll
    for (int rs = 0; rs < 4; ++rs) {
        int r = mr + (rs >> 1) * 16 + (rs & 1) * 8 + (lane >> 2);
        int o = (r * 16 + cid) * 3;
        md[o] = td0[rs]; md[o + 1] = td1[rs]; md[o + 2] = td2[rs];
        mi[o] = ti0[rs]; mi[o + 1] = ti1[rs]; mi[o + 2] = ti2[rs];
    }
    __syncthreads();
    if (tid < BM) {
        float b0 = 3.4e38f, b1 = 3.4e38f, b2 = 3.4e38f;
        int i0 = 0, i1 = 0, i2 = 0;
        #pragma unroll 4
        for (int e = 0; e < 48; ++e) {
            float d = md[tid * 48 + e];
            int ii = mi[tid * 48 + e];
            if (d < b2) {
                b2 = d; i2 = ii;
                if (b2 < b1) {
                    float t = b1; b1 = b2; b2 = t;
                    int u = i1; i1 = i2; i2 = u;
                    if (b1 < b0) {
                        t = b0; b0 = b1; b1 = t;
                        u = i0; i0 = i1; i1 = u;
                    }
                }
            }
        }
        int r = row0 + tid;
        g_cand[r * 3 + 0] = i0;
        g_cand[r * 3 + 1] = i1;
        g_cand[r * 3 + 2] = i2;
    }
}

// ---------------------------------------------------------------------------
// Fixup (exact fp32 rescore of 3 candidates) fused with gather.
// ---------------------------------------------------------------------------
__global__ void fixup_gather(const float* __restrict__ x,
                             const float* __restrict__ cb,
                             const float* __restrict__ values,
                             float* __restrict__ out) {
    const int row = (blockIdx.x * blockDim.x + threadIdx.x) >> 5;
    const int lane = threadIdx.x & 31;
    if (row >= NTOK) return;

    float4 xv[4];
    const float4* xr = reinterpret_cast<const float4*>(x + (size_t)row * KDIM);
    #pragma unroll
    for (int j = 0; j < 4; ++j) xv[j] = xr[lane + j * 32];

    float bd = 3.4e38f;
    int bi = NCODES;
    #pragma unroll
    for (int c = 0; c < 3; ++c) {
        int idx = g_cand[row * 3 + c];
        const float4* er = reinterpret_cast<const float4*>(cb + (size_t)idx * KDIM);
        float s = 0.f;
        #pragma unroll
        for (int j = 0; j < 4; ++j) {
            float4 e = er[lane + j * 32];
            s += xv[j].x * e.x + xv[j].y * e.y + xv[j].z * e.z + xv[j].w * e.w;
        }
        #pragma unroll
        for (int o = 16; o > 0; o >>= 1) s += __shfl_xor_sync(0xffffffffu, s, o);
        float d = fmaf(-2.f, s, d_esq[idx]);
        if (d < bd || (d == bd && idx < bi)) { bd = d; bi = idx; }
    }

    const float4* vr = reinterpret_cast<const float4*>(values + (size_t)bi * KDIM);
    float4* orow = reinterpret_cast<float4*>(out + (size_t)row * KDIM);
    #pragma unroll
    for (int j = 0; j < 4; ++j) orow[lane + j * 32] = vr[lane + j * 32];
}

// ---------------------------------------------------------------------------
extern "C" void kernel_launch(void* const* d_in, const int* in_sizes, int n_in,
                              void* d_out, int out_size) {
    const float* x      = (const float*)d_in[0];   // [16384, 512]
    const float* cb     = (const float*)d_in[1];   // [8192, 512]
    const float* values = (const float*)d_in[2];   // [8192, 512]
    float* out = (float*)d_out;

    cudaFuncSetAttribute(vq_main,
                         cudaFuncAttributeMaxDynamicSharedMemorySize, SMEM_TOTAL);

    esq_kernel<<<NCODES / 8, 256>>>(cb);
    conv_kernel<<<(NTOK * KDIM / 4) / 256, 256>>>(x, NTOK * KDIM / 4, 0);
    conv_kernel<<<(NCODES * KDIM / 4) / 256, 256>>>(cb, NCODES * KDIM / 4, 1);
    vq_main<<<NTOK / BM, NTHREADS, SMEM_TOTAL>>>();
    fixup_gather<<<(NTOK * 32) / 256, 256>>>(x, cb, values, out);
}

// round 11
// speedup vs baseline: 13.5834x; 1.3052x over previous
#include <cuda_runtime.h>
#include <cuda_bf16.h>
#include <cstdint>

// ============================================================================
// DiscreteKeyValueBottleneck — int8 mma.sync (m16n8k32) candidate GEMM +
// per-thread top-4 / global top-8 candidates + exact fp32 fixup + gather.
// ============================================================================

#define KDIM     512
#define NCODES   8192
#define NTOK     16384
#define BM       128                 // rows / CTA
#define BN       128                 // codes / tile
#define BKC      128                 // k elements per chunk (= 128 B rows)
#define NS       4                   // cp.async stages
#define KCHUNKS  (KDIM / BKC)        // 4
#define NTILES   (NCODES / BN)       // 64
#define NCHUNKS  (NTILES * KCHUNKS)  // 256
#define NTHREADS 512
#define NCAND    8                   // global candidates rescored exactly

#define XS_BYTES (BM * KDIM)         // 65536 (int8)
#define ST_BYTES (BN * BKC)          // 16384
#define SMEM_TOTAL (XS_BYTES + NS * ST_BYTES)  // 131072

#define QSCALE   (4.0f / 127.0f)
#define QINV     (127.0f / 4.0f)

__device__ int8_t g_x8[NTOK * KDIM];
__device__ int8_t g_e8[NCODES * KDIM];
__device__ float  d_esq[NCODES];
__device__ int    g_cand[NTOK * NCAND];

// ---------------------------------------------------------------------------
__device__ __forceinline__ uint32_t smem_u32(const void* p) {
    uint32_t a;
    asm("{ .reg .u64 t; cvta.to.shared.u64 t, %1; cvt.u32.u64 %0, t; }"
        : "=r"(a) : "l"(p));
    return a;
}
__device__ __forceinline__ void cp16(uint32_t dst, const void* src) {
    asm volatile("cp.async.cg.shared.global [%0], [%1], 16;"
                 :: "r"(dst), "l"(src) : "memory");
}
#define CP_COMMIT() asm volatile("cp.async.commit_group;" ::: "memory")

__device__ __forceinline__ void ldsm4(uint32_t* r, uint32_t addr) {
    asm volatile("ldmatrix.sync.aligned.m8n8.x4.shared.b16 {%0,%1,%2,%3}, [%4];"
                 : "=r"(r[0]), "=r"(r[1]), "=r"(r[2]), "=r"(r[3]) : "r"(addr));
}
__device__ __forceinline__ void imma16832(int* d, const uint32_t* a,
                                          const uint32_t* b) {
    asm volatile(
        "mma.sync.aligned.m16n8k32.row.col.s32.s8.s8.s32 "
        "{%0,%1,%2,%3}, {%4,%5,%6,%7}, {%8,%9}, {%0,%1,%2,%3};"
        : "+r"(d[0]), "+r"(d[1]), "+r"(d[2]), "+r"(d[3])
        : "r"(a[0]), "r"(a[1]), "r"(a[2]), "r"(a[3]), "r"(b[0]), "r"(b[1]));
}

// ---------------------------------------------------------------------------
// Pre-pass kernels
// ---------------------------------------------------------------------------
__global__ void esq_kernel(const float* __restrict__ cb) {
    int warp = (blockIdx.x * blockDim.x + threadIdx.x) >> 5;
    int lane = threadIdx.x & 31;
    if (warp >= NCODES) return;
    const float4* row = reinterpret_cast<const float4*>(cb + (size_t)warp * KDIM);
    float s = 0.f;
    #pragma unroll
    for (int i = 0; i < KDIM / 4 / 32; ++i) {
        float4 v = row[lane + i * 32];
        s += v.x * v.x + v.y * v.y + v.z * v.z + v.w * v.w;
    }
    #pragma unroll
    for (int o = 16; o > 0; o >>= 1) s += __shfl_xor_sync(0xffffffffu, s, o);
    if (lane == 0) d_esq[warp] = s;
}

__device__ __forceinline__ int qv(float v) {
    return __float2int_rn(fminf(fmaxf(v * QINV, -127.f), 127.f));
}
__global__ void conv_kernel(const float* __restrict__ src, int n4, int which) {
    int i = blockIdx.x * blockDim.x + threadIdx.x;
    if (i >= n4) return;
    int8_t* dst = which ? g_e8 : g_x8;
    float4 v = reinterpret_cast<const float4*>(src)[i];
    uint32_t p = (uint32_t)(qv(v.x) & 0xff) | ((uint32_t)(qv(v.y) & 0xff) << 8) |
                 ((uint32_t)(qv(v.z) & 0xff) << 16) | ((uint32_t)(qv(v.w) & 0xff) << 24);
    reinterpret_cast<uint32_t*>(dst)[i] = p;
}

// ---------------------------------------------------------------------------
// Main kernel
// ---------------------------------------------------------------------------
extern __shared__ __align__(1024) char smem[];

__device__ __forceinline__ void load_chunk(uint32_t st_u, int g, int tid) {
    const int nt = g >> 2, kc = g & 3, s = g & (NS - 1);
    const int8_t* src = g_e8 + (size_t)(nt * BN) * KDIM + kc * BKC;
    const uint32_t dst = st_u + s * ST_BYTES;
    #pragma unroll
    for (int i = 0; i < 2; ++i) {
        int idx = tid + i * NTHREADS;     // 1024 16B segs
        int c = idx >> 3, sg = idx & 7;
        cp16(dst + c * 128 + ((sg * 16) ^ ((c & 7) << 4)),
             src + (size_t)c * KDIM + sg * 16);
    }
}

// per-thread top-4 insertion (sorted ascending td[rs][0..3])
#define INS4(rs, d, i)                                                       \
    do {                                                                     \
        if ((d) < td[rs][3]) {                                               \
            td[rs][3] = (d); ti[rs][3] = (i);                                \
            if (td[rs][3] < td[rs][2]) {                                     \
                float _t = td[rs][2]; td[rs][2] = td[rs][3]; td[rs][3] = _t; \
                int _u = ti[rs][2]; ti[rs][2] = ti[rs][3]; ti[rs][3] = _u;   \
                if (td[rs][2] < td[rs][1]) {                                 \
                    _t = td[rs][1]; td[rs][1] = td[rs][2]; td[rs][2] = _t;   \
                    _u = ti[rs][1]; ti[rs][1] = ti[rs][2]; ti[rs][2] = _u;   \
                    if (td[rs][1] < td[rs][0]) {                             \
                        _t = td[rs][0]; td[rs][0] = td[rs][1]; td[rs][1] = _t;\
                        _u = ti[rs][0]; ti[rs][0] = ti[rs][1]; ti[rs][1] = _u;\
                    }                                                        \
                }                                                            \
            }                                                                \
        }                                                                    \
    } while (0)

__global__ __launch_bounds__(NTHREADS, 1) void vq_main() {
    const int tid = threadIdx.x, lane = tid & 31, wid = tid >> 5;
    const int row0 = blockIdx.x * BM;
    const uint32_t xs_u = smem_u32(smem);
    const uint32_t st_u = xs_u + XS_BYTES;

    // ---- resident x tile: 128 x 512 int8, swizzled (rows of 512 B) ----
    #pragma unroll 4
    for (int i = 0; i < (BM * KDIM / 16) / NTHREADS; ++i) {  // 8
        int idx = tid + i * NTHREADS;
        int r = idx >> 5, sg = idx & 31;
        cp16(xs_u + r * 512 + ((sg * 16) ^ ((r & 7) << 4)),
             g_x8 + (size_t)(row0 + r) * KDIM + sg * 16);
    }
    CP_COMMIT();
    #pragma unroll
    for (int g = 0; g < NS - 1; ++g) { load_chunk(st_u, g, tid); CP_COMMIT(); }

    const int rowg = wid >> 2, colg = wid & 3;
    const int mr = rowg * 32, nc = colg * 32;

    // ---- base swizzled ldsm addresses; ks applied via XOR (disjoint bits) ----
    uint32_t aBase[2], bBase[2];
    #pragma unroll
    for (int rg = 0; rg < 2; ++rg) {
        int r = mr + rg * 16 + (lane & 15);
        aBase[rg] = xs_u + r * 512 + (((lane >> 4) * 16) ^ ((r & 7) << 4));
    }
    #pragma unroll
    for (int p = 0; p < 2; ++p) {
        int c = nc + p * 16 + (lane & 7) + ((lane >> 4) & 1) * 8;
        bBase[p] = c * 128 + ((((lane >> 3) & 1) * 16) ^ ((c & 7) << 4));
    }

    float td[4][4];
    int   ti[4][4];
    #pragma unroll
    for (int i = 0; i < 4; ++i)
        #pragma unroll
        for (int j = 0; j < 4; ++j) { td[i][j] = 3.4e38f; ti[i][j] = 0; }

    int acc[2][4][4];
    const float nS2 = -2.0f * QSCALE * QSCALE;

    #pragma unroll 1
    for (int g = 0; g < NCHUNKS; ++g) {
        asm volatile("cp.async.wait_group %0;" :: "n"(NS - 2));
        __syncthreads();
        if (g + NS - 1 < NCHUNKS) load_chunk(st_u, g + NS - 1, tid);
        CP_COMMIT();

        const int kc = g & 3;
        if (kc == 0) {
            #pragma unroll
            for (int rg = 0; rg < 2; ++rg)
                #pragma unroll
                for (int nf = 0; nf < 4; ++nf)
                    #pragma unroll
                    for (int q = 0; q < 4; ++q) acc[rg][nf][q] = 0;
        }

        const uint32_t aOff = kc * 128;
        const uint32_t sbase = st_u + (g & (NS - 1)) * ST_BYTES;
        const uint32_t sb0 = sbase + bBase[0], sb1 = sbase + bBase[1];
        #pragma unroll
        for (int ks = 0; ks < 4; ++ks) {   // 4 x k32 = 128 k-elems
            const uint32_t kx = (uint32_t)(ks << 5);
            uint32_t a[2][4], b[2][4];
            ldsm4(a[0], (aBase[0] + aOff) ^ kx);
            ldsm4(a[1], (aBase[1] + aOff) ^ kx);
            ldsm4(b[0], sb0 ^ kx);
            ldsm4(b[1], sb1 ^ kx);
            #pragma unroll
            for (int rg = 0; rg < 2; ++rg)
                #pragma unroll
                for (int p = 0; p < 2; ++p)
                    #pragma unroll
                    for (int q = 0; q < 2; ++q)
                        imma16832(acc[rg][p * 2 + q], a[rg], b[p] + q * 2);
        }

        if (kc == 3) {
            const int code_base = (g >> 2) * BN + nc + (lane & 3) * 2;
            #pragma unroll
            for (int rg = 0; rg < 2; ++rg) {
                #pragma unroll
                for (int nf = 0; nf < 4; ++nf) {
                    const int cg0 = code_base + nf * 8;
                    const float e0 = __ldg(&d_esq[cg0]);
                    const float e1 = __ldg(&d_esq[cg0 + 1]);
                    float d;
                    d = fmaf(nS2, (float)acc[rg][nf][0], e0); INS4(rg * 2, d, cg0);
                    d = fmaf(nS2, (float)acc[rg][nf][1], e1); INS4(rg * 2, d, cg0 + 1);
                    d = fmaf(nS2, (float)acc[rg][nf][2], e0); INS4(rg * 2 + 1, d, cg0);
                    d = fmaf(nS2, (float)acc[rg][nf][3], e1); INS4(rg * 2 + 1, d, cg0 + 1);
                }
            }
        }
    }

    // ---- per-row merge of 64 candidates -> global top-8 ----
    __syncthreads();
    float* md = reinterpret_cast<float*>(smem + XS_BYTES);          // [128][16][4]
    int*   mi = reinterpret_cast<int*>(smem + XS_BYTES + 128 * 64 * 4);
    const int cid = colg * 4 + (lane & 3);
    #pragma unroll
    for (int rs = 0; rs < 4; ++rs) {
        int r = mr + (rs >> 1) * 16 + (rs & 1) * 8 + (lane >> 2);
        int o = (r * 16 + cid) * 4;
        #pragma unroll
        for (int j = 0; j < 4; ++j) { md[o + j] = td[rs][j]; mi[o + j] = ti[rs][j]; }
    }
    __syncthreads();
    if (tid < BM) {
        float b0 = 3.4e38f, b1 = 3.4e38f, b2 = 3.4e38f, b3 = 3.4e38f;
        float b4 = 3.4e38f, b5 = 3.4e38f, b6 = 3.4e38f, b7 = 3.4e38f;
        int i0 = 0, i1 = 0, i2 = 0, i3 = 0, i4 = 0, i5 = 0, i6 = 0, i7 = 0;
        #pragma unroll 4
        for (int e = 0; e < 64; ++e) {
            float d = md[tid * 64 + e];
            int ii = mi[tid * 64 + e];
            if (d < b7) {
                b7 = d; i7 = ii;
                if (b7 < b6) { float t=b6;b6=b7;b7=t; int u=i6;i6=i7;i7=u;
                 if (b6 < b5) { t=b5;b5=b6;b6=t; u=i5;i5=i6;i6=u;
                  if (b5 < b4) { t=b4;b4=b5;b5=t; u=i4;i4=i5;i5=u;
                   if (b4 < b3) { t=b3;b3=b4;b4=t; u=i3;i3=i4;i4=u;
                    if (b3 < b2) { t=b2;b2=b3;b3=t; u=i2;i2=i3;i3=u;
                     if (b2 < b1) { t=b1;b1=b2;b2=t; u=i1;i1=i2;i2=u;
                      if (b1 < b0) { t=b0;b0=b1;b1=t; u=i0;i0=i1;i1=u; }}}}}}}
            }
        }
        int r = row0 + tid;
        g_cand[r * NCAND + 0] = i0; g_cand[r * NCAND + 1] = i1;
        g_cand[r * NCAND + 2] = i2; g_cand[r * NCAND + 3] = i3;
        g_cand[r * NCAND + 4] = i4; g_cand[r * NCAND + 5] = i5;
        g_cand[r * NCAND + 6] = i6; g_cand[r * NCAND + 7] = i7;
    }
}

// ---------------------------------------------------------------------------
// Fixup (exact fp32 rescore of NCAND candidates) fused with gather.
// ---------------------------------------------------------------------------
__global__ void fixup_gather(const float* __restrict__ x,
                             const float* __restrict__ cb,
                             const float* __restrict__ values,
                             float* __restrict__ out) {
    const int row = (blockIdx.x * blockDim.x + threadIdx.x) >> 5;
    const int lane = threadIdx.x & 31;
    if (row >= NTOK) return;

    float4 xv[4];
    const float4* xr = reinterpret_cast<const float4*>(x + (size_t)row * KDIM);
    #pragma unroll
    for (int j = 0; j < 4; ++j) xv[j] = xr[lane + j * 32];

    float bd = 3.4e38f;
    int bi = NCODES;
    #pragma unroll
    for (int c = 0; c < NCAND; ++c) {
        int idx = g_cand[row * NCAND + c];
        const float4* er = reinterpret_cast<const float4*>(cb + (size_t)idx * KDIM);
        float s = 0.f;
        #pragma unroll
        for (int j = 0; j < 4; ++j) {
            float4 e = er[lane + j * 32];
            s += xv[j].x * e.x + xv[j].y * e.y + xv[j].z * e.z + xv[j].w * e.w;
        }
        #pragma unroll
        for (int o = 16; o > 0; o >>= 1) s += __shfl_xor_sync(0xffffffffu, s, o);
        float d = fmaf(-2.f, s, d_esq[idx]);
        if (d < bd || (d == bd && idx < bi)) { bd = d; bi = idx; }
    }

    const float4* vr = reinterpret_cast<const float4*>(values + (size_t)bi * KDIM);
    float4* orow = reinterpret_cast<float4*>(out + (size_t)row * KDIM);
    #pragma unroll
    for (int j = 0; j < 4; ++j) orow[lane + j * 32] = vr[lane + j * 32];
}

// ---------------------------------------------------------------------------
extern "C" void kernel_launch(void* const* d_in, const int* in_sizes, int n_in,
                              void* d_out, int out_size) {
    const float* x      = (const float*)d_in[0];   // [16384, 512]
    const float* cb     = (const float*)d_in[1];   // [8192, 512]
    const float* values = (const float*)d_in[2];   // [8192, 512]
    float* out = (float*)d_out;

    cudaFuncSetAttribute(vq_main,
                         cudaFuncAttributeMaxDynamicSharedMemorySize, SMEM_TOTAL);

    esq_kernel<<<NCODES / 8, 256>>>(cb);
    conv_kernel<<<(NTOK * KDIM / 4) / 256, 256>>>(x, NTOK * KDIM / 4, 0);
    conv_kernel<<<(NCODES * KDIM / 4) / 256, 256>>>(cb, NCODES * KDIM / 4, 1);
    vq_main<<<NTOK / BM, NTHREADS, SMEM_TOTAL>>>();
    fixup_gather<<<(NTOK * 32) / 256, 256>>>(x, cb, values, out);
}

// round 13
// speedup vs baseline: 17.8320x; 1.3128x over previous
#include <cuda_runtime.h>
#include <cuda_bf16.h>
#include <cstdint>

// ============================================================================
// DiscreteKeyValueBottleneck — int8 mma.sync (m16n8k32) candidate GEMM with
// whole-tile staging, hoisted addresses, integer packed-distance top-4/top-8
// selection + exact fp32 fixup + fused gather.
// ============================================================================

#define KDIM     512
#define NCODES   8192
#define NTOK     16384
#define BM       128                 // rows / CTA
#define BN       128                 // codes / tile
#define NTILES   (NCODES / BN)       // 64
#define NTHREADS 512
#define NCAND    8

#define XS_BYTES   (BM * KDIM)       // 65536 (int8)
#define TILE_BYTES (BN * KDIM)       // 65536 (full-K code tile)
#define SMEM_TOTAL (XS_BYTES + 2 * TILE_BYTES)  // 196608

#define QSCALE   (4.0f / 127.0f)
#define QINV     (127.0f / 4.0f)
#define EBIAS    400000

__device__ int8_t g_x8[NTOK * KDIM];
__device__ int8_t g_e8[NCODES * KDIM];
__device__ float  d_esq[NCODES];
__device__ int    g_esqi[NCODES];
__device__ int    g_cand[NTOK * NCAND];

// ---------------------------------------------------------------------------
__device__ __forceinline__ uint32_t smem_u32(const void* p) {
    uint32_t a;
    asm("{ .reg .u64 t; cvta.to.shared.u64 t, %1; cvt.u32.u64 %0, t; }"
        : "=r"(a) : "l"(p));
    return a;
}
__device__ __forceinline__ void cp16(uint32_t dst, const void* src) {
    asm volatile("cp.async.cg.shared.global [%0], [%1], 16;"
                 :: "r"(dst), "l"(src) : "memory");
}
#define CP_COMMIT() asm volatile("cp.async.commit_group;" ::: "memory")

__device__ __forceinline__ void ldsm4(uint32_t* r, uint32_t addr) {
    asm volatile("ldmatrix.sync.aligned.m8n8.x4.shared.b16 {%0,%1,%2,%3}, [%4];"
                 : "=r"(r[0]), "=r"(r[1]), "=r"(r[2]), "=r"(r[3]) : "r"(addr));
}
__device__ __forceinline__ void imma16832(int* d, const uint32_t* a,
                                          const uint32_t* b) {
    asm volatile(
        "mma.sync.aligned.m16n8k32.row.col.s32.s8.s8.s32 "
        "{%0,%1,%2,%3}, {%4,%5,%6,%7}, {%8,%9}, {%0,%1,%2,%3};"
        : "+r"(d[0]), "+r"(d[1]), "+r"(d[2]), "+r"(d[3])
        : "r"(a[0]), "r"(a[1]), "r"(a[2]), "r"(a[3]), "r"(b[0]), "r"(b[1]));
}

// ---------------------------------------------------------------------------
// Pre-pass kernels
// ---------------------------------------------------------------------------
__global__ void esq_kernel(const float* __restrict__ cb) {
    int warp = (blockIdx.x * blockDim.x + threadIdx.x) >> 5;
    int lane = threadIdx.x & 31;
    if (warp >= NCODES) return;
    const float4* row = reinterpret_cast<const float4*>(cb + (size_t)warp * KDIM);
    float s = 0.f;
    #pragma unroll
    for (int i = 0; i < KDIM / 4 / 32; ++i) {
        float4 v = row[lane + i * 32];
        s += v.x * v.x + v.y * v.y + v.z * v.z + v.w * v.w;
    }
    #pragma unroll
    for (int o = 16; o > 0; o >>= 1) s += __shfl_xor_sync(0xffffffffu, s, o);
    if (lane == 0) {
        d_esq[warp] = s;
        // distance unit = 2*QSCALE^2 ; bias keeps d = esqi - dot_int positive
        g_esqi[warp] = __float2int_rn(s / (2.0f * QSCALE * QSCALE)) + EBIAS;
    }
}

__device__ __forceinline__ int qv(float v) {
    return __float2int_rn(fminf(fmaxf(v * QINV, -127.f), 127.f));
}
__global__ void conv_kernel(const float* __restrict__ src, int n4, int which) {
    int i = blockIdx.x * blockDim.x + threadIdx.x;
    if (i >= n4) return;
    int8_t* dst = which ? g_e8 : g_x8;
    float4 v = reinterpret_cast<const float4*>(src)[i];
    uint32_t p = (uint32_t)(qv(v.x) & 0xff) | ((uint32_t)(qv(v.y) & 0xff) << 8) |
                 ((uint32_t)(qv(v.z) & 0xff) << 16) | ((uint32_t)(qv(v.w) & 0xff) << 24);
    reinterpret_cast<uint32_t*>(dst)[i] = p;
}

// ---------------------------------------------------------------------------
// Main kernel
// ---------------------------------------------------------------------------
extern __shared__ __align__(1024) char smem[];

__device__ __forceinline__ void load_tile(uint32_t dst, int nt, int tid) {
    const int8_t* src = g_e8 + (size_t)(nt * BN) * KDIM;
    #pragma unroll
    for (int i = 0; i < (BN * KDIM / 16) / NTHREADS; ++i) {  // 8
        int idx = tid + i * NTHREADS;          // 4096 16B segs
        int c = idx >> 5, sg = idx & 31;       // 32 segs per 512B code row
        cp16(dst + c * 512 + ((sg * 16) ^ ((c & 7) << 4)),
             src + (size_t)c * KDIM + sg * 16);
    }
}

// packed-int top-4 insertion (sorted ascending td[rs][0..3])
#define INS4P(rs, v)                                                         \
    do {                                                                     \
        if ((v) < td[rs][3]) {                                               \
            td[rs][3] = (v);                                                 \
            if (td[rs][3] < td[rs][2]) {                                     \
                int _t = td[rs][2]; td[rs][2] = td[rs][3]; td[rs][3] = _t;   \
                if (td[rs][2] < td[rs][1]) {                                 \
                    _t = td[rs][1]; td[rs][1] = td[rs][2]; td[rs][2] = _t;   \
                    if (td[rs][1] < td[rs][0]) {                             \
                        _t = td[rs][0]; td[rs][0] = td[rs][1]; td[rs][1] = _t;\
                    }                                                        \
                }                                                            \
            }                                                                \
        }                                                                    \
    } while (0)

__device__ __forceinline__ int packd(int d, int code) {
    d = min(max(d, 0), 1048575);               // 20-bit clamp (safety)
    return ((d >> 2) << 13) | code;            // 18-bit dist | 13-bit code
}

__global__ __launch_bounds__(NTHREADS, 1) void vq_main() {
    const int tid = threadIdx.x, lane = tid & 31, wid = tid >> 5;
    const int row0 = blockIdx.x * BM;
    const uint32_t xs_u = smem_u32(smem);
    const uint32_t st_u = xs_u + XS_BYTES;

    // ---- resident x tile: 128 x 512 int8, swizzled rows of 512 B ----
    #pragma unroll 4
    for (int i = 0; i < (BM * KDIM / 16) / NTHREADS; ++i) {  // 8
        int idx = tid + i * NTHREADS;
        int r = idx >> 5, sg = idx & 31;
        cp16(xs_u + r * 512 + ((sg * 16) ^ ((r & 7) << 4)),
             g_x8 + (size_t)(row0 + r) * KDIM + sg * 16);
    }
    load_tile(st_u, 0, tid);
    CP_COMMIT();

    const int rowg = wid >> 2, colg = wid & 3;
    const int mr = rowg * 32, nc = colg * 32;

    // ---- hoisted swizzled ldsm addresses (ks folded via XOR, kc via +128) --
    uint32_t aX[4][2], bX[4][2];
    #pragma unroll
    for (int rg = 0; rg < 2; ++rg) {
        int r = mr + rg * 16 + (lane & 15);
        uint32_t base = xs_u + r * 512 + (((lane >> 4) * 16) ^ ((r & 7) << 4));
        #pragma unroll
        for (int ks = 0; ks < 4; ++ks) aX[ks][rg] = base ^ (uint32_t)(ks << 5);
    }
    #pragma unroll
    for (int p = 0; p < 2; ++p) {
        int c = nc + p * 16 + (lane & 7) + ((lane >> 4) & 1) * 8;
        uint32_t base = (uint32_t)(c * 512) +
                        ((((lane >> 3) & 1) * 16) ^ ((c & 7) << 4));
        #pragma unroll
        for (int ks = 0; ks < 4; ++ks) bX[ks][p] = base ^ (uint32_t)(ks << 5);
    }

    int td[4][4];
    #pragma unroll
    for (int i = 0; i < 4; ++i)
        #pragma unroll
        for (int j = 0; j < 4; ++j) td[i][j] = 0x7FFFFFFF;

    int acc[2][4][4];

    #pragma unroll 1
    for (int nt = 0; nt < NTILES; ++nt) {
        asm volatile("cp.async.wait_group 0;" ::: "memory");
        __syncthreads();
        if (nt + 1 < NTILES) {
            load_tile(st_u + ((nt + 1) & 1) * TILE_BYTES, nt + 1, tid);
            CP_COMMIT();
        }
        const uint32_t bufb = st_u + (nt & 1) * TILE_BYTES;

        #pragma unroll
        for (int rg = 0; rg < 2; ++rg)
            #pragma unroll
            for (int nf = 0; nf < 4; ++nf)
                #pragma unroll
                for (int q = 0; q < 4; ++q) acc[rg][nf][q] = 0;

        #pragma unroll
        for (int kc = 0; kc < 4; ++kc) {
            const uint32_t kcoff = (uint32_t)(kc * 128);
            #pragma unroll
            for (int ks = 0; ks < 4; ++ks) {
                uint32_t a[2][4], b[2][4];
                ldsm4(a[0], aX[ks][0] + kcoff);
                ldsm4(a[1], aX[ks][1] + kcoff);
                ldsm4(b[0], bufb + bX[ks][0] + kcoff);
                ldsm4(b[1], bufb + bX[ks][1] + kcoff);
                #pragma unroll
                for (int rg = 0; rg < 2; ++rg)
                    #pragma unroll
                    for (int p = 0; p < 2; ++p)
                        #pragma unroll
                        for (int q = 0; q < 2; ++q)
                            imma16832(acc[rg][p * 2 + q], a[rg], b[p] + q * 2);
            }
        }

        // ---- integer epilogue: d = esqi - dot ; packed top-4 ----
        const int code_base = nt * BN + nc + (lane & 3) * 2;
        #pragma unroll
        for (int rg = 0; rg < 2; ++rg) {
            #pragma unroll
            for (int nf = 0; nf < 4; ++nf) {
                const int cg0 = code_base + nf * 8;
                const int2 ei = __ldg(reinterpret_cast<const int2*>(&g_esqi[cg0]));
                int v;
                v = packd(ei.x - acc[rg][nf][0], cg0);     INS4P(rg * 2, v);
                v = packd(ei.y - acc[rg][nf][1], cg0 + 1); INS4P(rg * 2, v);
                v = packd(ei.x - acc[rg][nf][2], cg0);     INS4P(rg * 2 + 1, v);
                v = packd(ei.y - acc[rg][nf][3], cg0 + 1); INS4P(rg * 2 + 1, v);
            }
        }
    }

    // ---- per-row merge of 64 packed candidates -> global top-8 ----
    __syncthreads();
    int* md = reinterpret_cast<int*>(smem + XS_BYTES);      // [128][68] padded
    const int cid = colg * 4 + (lane & 3);
    #pragma unroll
    for (int rs = 0; rs < 4; ++rs) {
        int r = mr + (rs >> 1) * 16 + (rs & 1) * 8 + (lane >> 2);
        int o = r * 68 + cid * 4;
        #pragma unroll
        for (int j = 0; j < 4; ++j) md[o + j] = td[rs][j];
    }
    __syncthreads();
    if (tid < BM) {
        int b0 = 0x7FFFFFFF, b1 = 0x7FFFFFFF, b2 = 0x7FFFFFFF, b3 = 0x7FFFFFFF;
        int b4 = 0x7FFFFFFF, b5 = 0x7FFFFFFF, b6 = 0x7FFFFFFF, b7 = 0x7FFFFFFF;
        #pragma unroll 4
        for (int e = 0; e < 64; ++e) {
            int v = md[tid * 68 + e];
            if (v < b7) {
                b7 = v;
                if (b7 < b6) { int t=b6;b6=b7;b7=t;
                 if (b6 < b5) { t=b5;b5=b6;b6=t;
                  if (b5 < b4) { t=b4;b4=b5;b5=t;
                   if (b4 < b3) { t=b3;b3=b4;b4=t;
                    if (b3 < b2) { t=b2;b2=b3;b3=t;
                     if (b2 < b1) { t=b1;b1=b2;b2=t;
                      if (b1 < b0) { t=b0;b0=b1;b1=t; }}}}}}}
            }
        }
        int r = row0 + tid;
        g_cand[r * NCAND + 0] = b0 & 8191; g_cand[r * NCAND + 1] = b1 & 8191;
        g_cand[r * NCAND + 2] = b2 & 8191; g_cand[r * NCAND + 3] = b3 & 8191;
        g_cand[r * NCAND + 4] = b4 & 8191; g_cand[r * NCAND + 5] = b5 & 8191;
        g_cand[r * NCAND + 6] = b6 & 8191; g_cand[r * NCAND + 7] = b7 & 8191;
    }
}

// ---------------------------------------------------------------------------
// Fixup (exact fp32 rescore of NCAND candidates) fused with gather.
// ---------------------------------------------------------------------------
__global__ void fixup_gather(const float* __restrict__ x,
                             const float* __restrict__ cb,
                             const float* __restrict__ values,
                             float* __restrict__ out) {
    const int row = (blockIdx.x * blockDim.x + threadIdx.x) >> 5;
    const int lane = threadIdx.x & 31;
    if (row >= NTOK) return;

    float4 xv[4];
    const float4* xr = reinterpret_cast<const float4*>(x + (size_t)row * KDIM);
    #pragma unroll
    for (int j = 0; j < 4; ++j) xv[j] = xr[lane + j * 32];

    float bd = 3.4e38f;
    int bi = NCODES;
    #pragma unroll
    for (int c = 0; c < NCAND; ++c) {
        int idx = g_cand[row * NCAND + c];
        const float4* er = reinterpret_cast<const float4*>(cb + (size_t)idx * KDIM);
        float s = 0.f;
        #pragma unroll
        for (int j = 0; j < 4; ++j) {
            float4 e = er[lane + j * 32];
            s += xv[j].x * e.x + xv[j].y * e.y + xv[j].z * e.z + xv[j].w * e.w;
        }
        #pragma unroll
        for (int o = 16; o > 0; o >>= 1) s += __shfl_xor_sync(0xffffffffu, s, o);
        float d = fmaf(-2.f, s, d_esq[idx]);
        if (d < bd || (d == bd && idx < bi)) { bd = d; bi = idx; }
    }

    const float4* vr = reinterpret_cast<const float4*>(values + (size_t)bi * KDIM);
    float4* orow = reinterpret_cast<float4*>(out + (size_t)row * KDIM);
    #pragma unroll
    for (int j = 0; j < 4; ++j) orow[lane + j * 32] = vr[lane + j * 32];
}

// ---------------------------------------------------------------------------
extern "C" void kernel_launch(void* const* d_in, const int* in_sizes, int n_in,
                              void* d_out, int out_size) {
    const float* x      = (const float*)d_in[0];   // [16384, 512]
    const float* cb     = (const float*)d_in[1];   // [8192, 512]
    const float* values = (const float*)d_in[2];   // [8192, 512]
    float* out = (float*)d_out;

    cudaFuncSetAttribute(vq_main,
                         cudaFuncAttributeMaxDynamicSharedMemorySize, SMEM_TOTAL);

    esq_kernel<<<NCODES / 8, 256>>>(cb);
    conv_kernel<<<(NTOK * KDIM / 4) / 256, 256>>>(x, NTOK * KDIM / 4, 0);
    conv_kernel<<<(NCODES * KDIM / 4) / 256, 256>>>(cb, NCODES * KDIM / 4, 1);
    vq_main<<<NTOK / BM, NTHREADS, SMEM_TOTAL>>>();
    fixup_gather<<<(NTOK * 32) / 256, 256>>>(x, cb, values, out);
}

// round 14
// speedup vs baseline: 18.3747x; 1.0304x over previous
#include <cuda_runtime.h>
#include <cuda_bf16.h>
#include <cstdint>

// ============================================================================
// DiscreteKeyValueBottleneck — int8 mma.sync (m16n8k32) with NEGATED codebook
// and esq-preloaded accumulators (acc ends as the distance directly),
// packed-int top-4/top-8 selection + exact fp32 fixup + fused gather.
// ============================================================================

#define KDIM     512
#define NCODES   8192
#define NTOK     16384
#define BM       128                 // rows / CTA
#define BN       128                 // codes / tile
#define NTILES   (NCODES / BN)       // 64
#define NTHREADS 512
#define NCAND    8

#define XS_BYTES   (BM * KDIM)       // 65536 (int8)
#define TILE_BYTES (BN * KDIM)       // 65536 (full-K code tile)
#define SMEM_TOTAL (XS_BYTES + 2 * TILE_BYTES)  // 196608

#define QSCALE   (4.0f / 127.0f)
#define QINV     (127.0f / 4.0f)
#define EBIAS    400000

__device__ int8_t g_x8[NTOK * KDIM];
__device__ int8_t g_e8[NCODES * KDIM];        // NEGATED quantized codebook
__device__ float  d_esq[NCODES];
__device__ int    g_esqi[NCODES];
__device__ int4   g_esqi2[NCODES / 2];        // {e0,e1,e0,e1} per code pair
__device__ int    g_cand[NTOK * NCAND];

// ---------------------------------------------------------------------------
__device__ __forceinline__ uint32_t smem_u32(const void* p) {
    uint32_t a;
    asm("{ .reg .u64 t; cvta.to.shared.u64 t, %1; cvt.u32.u64 %0, t; }"
        : "=r"(a) : "l"(p));
    return a;
}
__device__ __forceinline__ void cp16(uint32_t dst, const void* src) {
    asm volatile("cp.async.cg.shared.global [%0], [%1], 16;"
                 :: "r"(dst), "l"(src) : "memory");
}
#define CP_COMMIT() asm volatile("cp.async.commit_group;" ::: "memory")

__device__ __forceinline__ void ldsm4(uint32_t* r, uint32_t addr) {
    asm volatile("ldmatrix.sync.aligned.m8n8.x4.shared.b16 {%0,%1,%2,%3}, [%4];"
                 : "=r"(r[0]), "=r"(r[1]), "=r"(r[2]), "=r"(r[3]) : "r"(addr));
}
__device__ __forceinline__ void imma16832(int* d, const uint32_t* a,
                                          const uint32_t* b) {
    asm volatile(
        "mma.sync.aligned.m16n8k32.row.col.s32.s8.s8.s32 "
        "{%0,%1,%2,%3}, {%4,%5,%6,%7}, {%8,%9}, {%0,%1,%2,%3};"
        : "+r"(d[0]), "+r"(d[1]), "+r"(d[2]), "+r"(d[3])
        : "r"(a[0]), "r"(a[1]), "r"(a[2]), "r"(a[3]), "r"(b[0]), "r"(b[1]));
}

// ---------------------------------------------------------------------------
// Pre-pass kernels
// ---------------------------------------------------------------------------
__global__ void esq_kernel(const float* __restrict__ cb) {
    int warp = (blockIdx.x * blockDim.x + threadIdx.x) >> 5;
    int lane = threadIdx.x & 31;
    if (warp >= NCODES) return;
    const float4* row = reinterpret_cast<const float4*>(cb + (size_t)warp * KDIM);
    float s = 0.f;
    #pragma unroll
    for (int i = 0; i < KDIM / 4 / 32; ++i) {
        float4 v = row[lane + i * 32];
        s += v.x * v.x + v.y * v.y + v.z * v.z + v.w * v.w;
    }
    #pragma unroll
    for (int o = 16; o > 0; o >>= 1) s += __shfl_xor_sync(0xffffffffu, s, o);
    if (lane == 0) {
        d_esq[warp] = s;
        g_esqi[warp] = __float2int_rn(s / (2.0f * QSCALE * QSCALE)) + EBIAS;
    }
}

__global__ void esq2_kernel() {
    int i = blockIdx.x * blockDim.x + threadIdx.x;   // pair index
    if (i >= NCODES / 2) return;
    int a = g_esqi[2 * i], b = g_esqi[2 * i + 1];
    g_esqi2[i] = make_int4(a, b, a, b);
}

__device__ __forceinline__ int qv(float v) {
    return __float2int_rn(fminf(fmaxf(v * QINV, -127.f), 127.f));
}
__global__ void conv_kernel(const float* __restrict__ src, int n4, int which) {
    int i = blockIdx.x * blockDim.x + threadIdx.x;
    if (i >= n4) return;
    int8_t* dst = which ? g_e8 : g_x8;
    float4 v = reinterpret_cast<const float4*>(src)[i];
    int q0 = qv(v.x), q1 = qv(v.y), q2 = qv(v.z), q3 = qv(v.w);
    if (which) { q0 = -q0; q1 = -q1; q2 = -q2; q3 = -q3; }   // negate codebook
    uint32_t p = (uint32_t)(q0 & 0xff) | ((uint32_t)(q1 & 0xff) << 8) |
                 ((uint32_t)(q2 & 0xff) << 16) | ((uint32_t)(q3 & 0xff) << 24);
    reinterpret_cast<uint32_t*>(dst)[i] = p;
}

// ---------------------------------------------------------------------------
// Main kernel
// ---------------------------------------------------------------------------
extern __shared__ __align__(1024) char smem[];

__device__ __forceinline__ void load_tile(uint32_t dst, int nt, int tid) {
    const int8_t* src = g_e8 + (size_t)(nt * BN) * KDIM;
    #pragma unroll
    for (int i = 0; i < (BN * KDIM / 16) / NTHREADS; ++i) {  // 8
        int idx = tid + i * NTHREADS;          // 4096 16B segs
        int c = idx >> 5, sg = idx & 31;       // 32 segs per 512B code row
        cp16(dst + c * 512 + ((sg * 16) ^ ((c & 7) << 4)),
             src + (size_t)c * KDIM + sg * 16);
    }
}

// packed-int top-4 insertion (sorted ascending td[rs][0..3])
#define INS4P(rs, v)                                                         \
    do {                                                                     \
        if ((v) < td[rs][3]) {                                               \
            td[rs][3] = (v);                                                 \
            if (td[rs][3] < td[rs][2]) {                                     \
                int _t = td[rs][2]; td[rs][2] = td[rs][3]; td[rs][3] = _t;   \
                if (td[rs][2] < td[rs][1]) {                                 \
                    _t = td[rs][1]; td[rs][1] = td[rs][2]; td[rs][2] = _t;   \
                    if (td[rs][1] < td[rs][0]) {                             \
                        _t = td[rs][0]; td[rs][0] = td[rs][1]; td[rs][1] = _t;\
                    }                                                        \
                }                                                            \
            }                                                                \
        }                                                                    \
    } while (0)

// v = (d>>3)<<13 | code  ==  (d<<10) & ~0x1FFF | code   (d >= 0 guaranteed;
// 21-bit distance field covers worst-case d ~1.25M; granularity 8 units =
// 0.016 distance << sigma 0.58)
#define PACKV(d, code) ((((d) << 10) & 0xFFFFE000) | (code))

__global__ __launch_bounds__(NTHREADS, 1) void vq_main() {
    const int tid = threadIdx.x, lane = tid & 31, wid = tid >> 5;
    const int row0 = blockIdx.x * BM;
    const uint32_t xs_u = smem_u32(smem);
    const uint32_t st_u = xs_u + XS_BYTES;

    // ---- resident x tile: 128 x 512 int8, swizzled rows of 512 B ----
    #pragma unroll 4
    for (int i = 0; i < (BM * KDIM / 16) / NTHREADS; ++i) {  // 8
        int idx = tid + i * NTHREADS;
        int r = idx >> 5, sg = idx & 31;
        cp16(xs_u + r * 512 + ((sg * 16) ^ ((r & 7) << 4)),
             g_x8 + (size_t)(row0 + r) * KDIM + sg * 16);
    }
    load_tile(st_u, 0, tid);
    CP_COMMIT();

    const int rowg = wid >> 2, colg = wid & 3;
    const int mr = rowg * 32, nc = colg * 32;

    // ---- hoisted swizzled ldsm addresses (ks folded via XOR, kc via +128) --
    uint32_t aX[4][2], bX[4][2];
    #pragma unroll
    for (int rg = 0; rg < 2; ++rg) {
        int r = mr + rg * 16 + (lane & 15);
        uint32_t base = xs_u + r * 512 + (((lane >> 4) * 16) ^ ((r & 7) << 4));
        #pragma unroll
        for (int ks = 0; ks < 4; ++ks) aX[ks][rg] = base ^ (uint32_t)(ks << 5);
    }
    #pragma unroll
    for (int p = 0; p < 2; ++p) {
        int c = nc + p * 16 + (lane & 7) + ((lane >> 4) & 1) * 8;
        uint32_t base = (uint32_t)(c * 512) +
                        ((((lane >> 3) & 1) * 16) ^ ((c & 7) << 4));
        #pragma unroll
        for (int ks = 0; ks < 4; ++ks) bX[ks][p] = base ^ (uint32_t)(ks << 5);
    }

    int td[4][4];
    #pragma unroll
    for (int i = 0; i < 4; ++i)
        #pragma unroll
        for (int j = 0; j < 4; ++j) td[i][j] = 0x7FFFFFFF;

    int acc[2][4][4];
    const int cb_lane = nc + (lane & 3) * 2;   // code offset within tile

    #pragma unroll 1
    for (int nt = 0; nt < NTILES; ++nt) {
        asm volatile("cp.async.wait_group 0;" ::: "memory");
        __syncthreads();
        if (nt + 1 < NTILES) {
            load_tile(st_u + ((nt + 1) & 1) * TILE_BYTES, nt + 1, tid);
            CP_COMMIT();
        }
        const uint32_t bufb = st_u + (nt & 1) * TILE_BYTES;
        const int code_base = nt * BN + cb_lane;

        // acc init = integer e_sq (duplicated pairs) -> MMA yields distance
        #pragma unroll
        for (int nf = 0; nf < 4; ++nf) {
            const int4 t = __ldg(&g_esqi2[(code_base + nf * 8) >> 1]);
            #pragma unroll
            for (int rg = 0; rg < 2; ++rg) {
                acc[rg][nf][0] = t.x; acc[rg][nf][1] = t.y;
                acc[rg][nf][2] = t.z; acc[rg][nf][3] = t.w;
            }
        }

        #pragma unroll
        for (int kc = 0; kc < 4; ++kc) {
            const uint32_t kcoff = (uint32_t)(kc * 128);
            #pragma unroll
            for (int ks = 0; ks < 4; ++ks) {
                uint32_t a[2][4], b[2][4];
                ldsm4(a[0], aX[ks][0] + kcoff);
                ldsm4(a[1], aX[ks][1] + kcoff);
                ldsm4(b[0], bufb + bX[ks][0] + kcoff);
                ldsm4(b[1], bufb + bX[ks][1] + kcoff);
                #pragma unroll
                for (int rg = 0; rg < 2; ++rg)
                    #pragma unroll
                    for (int p = 0; p < 2; ++p)
                        #pragma unroll
                        for (int q = 0; q < 2; ++q)
                            imma16832(acc[rg][p * 2 + q], a[rg], b[p] + q * 2);
            }
        }

        // ---- epilogue: acc IS the distance; pack + top-4 insert ----
        #pragma unroll
        for (int rg = 0; rg < 2; ++rg) {
            #pragma unroll
            for (int nf = 0; nf < 4; ++nf) {
                const int cg0 = code_base + nf * 8;
                int v;
                v = PACKV(acc[rg][nf][0], cg0);     INS4P(rg * 2, v);
                v = PACKV(acc[rg][nf][1], cg0 + 1); INS4P(rg * 2, v);
                v = PACKV(acc[rg][nf][2], cg0);     INS4P(rg * 2 + 1, v);
                v = PACKV(acc[rg][nf][3], cg0 + 1); INS4P(rg * 2 + 1, v);
            }
        }
    }

    // ---- per-row merge of 64 packed candidates -> global top-8 ----
    __syncthreads();
    int* md = reinterpret_cast<int*>(smem + XS_BYTES);      // [128][68] padded
    const int cid = colg * 4 + (lane & 3);
    #pragma unroll
    for (int rs = 0; rs < 4; ++rs) {
        int r = mr + (rs >> 1) * 16 + (rs & 1) * 8 + (lane >> 2);
        int o = r * 68 + cid * 4;
        #pragma unroll
        for (int j = 0; j < 4; ++j) md[o + j] = td[rs][j];
    }
    __syncthreads();
    if (tid < BM) {
        int b0 = 0x7FFFFFFF, b1 = 0x7FFFFFFF, b2 = 0x7FFFFFFF, b3 = 0x7FFFFFFF;
        int b4 = 0x7FFFFFFF, b5 = 0x7FFFFFFF, b6 = 0x7FFFFFFF, b7 = 0x7FFFFFFF;
        #pragma unroll 4
        for (int e = 0; e < 64; ++e) {
            int v = md[tid * 68 + e];
            if (v < b7) {
                b7 = v;
                if (b7 < b6) { int t=b6;b6=b7;b7=t;
                 if (b6 < b5) { t=b5;b5=b6;b6=t;
                  if (b5 < b4) { t=b4;b4=b5;b5=t;
                   if (b4 < b3) { t=b3;b3=b4;b4=t;
                    if (b3 < b2) { t=b2;b2=b3;b3=t;
                     if (b2 < b1) { t=b1;b1=b2;b2=t;
                      if (b1 < b0) { t=b0;b0=b1;b1=t; }}}}}}}
            }
        }
        int r = row0 + tid;
        g_cand[r * NCAND + 0] = b0 & 8191; g_cand[r * NCAND + 1] = b1 & 8191;
        g_cand[r * NCAND + 2] = b2 & 8191; g_cand[r * NCAND + 3] = b3 & 8191;
        g_cand[r * NCAND + 4] = b4 & 8191; g_cand[r * NCAND + 5] = b5 & 8191;
        g_cand[r * NCAND + 6] = b6 & 8191; g_cand[r * NCAND + 7] = b7 & 8191;
    }
}

// ---------------------------------------------------------------------------
// Fixup (exact fp32 rescore of NCAND candidates) fused with gather.
// ---------------------------------------------------------------------------
__global__ void fixup_gather(const float* __restrict__ x,
                             const float* __restrict__ cb,
                             const float* __restrict__ values,
                             float* __restrict__ out) {
    const int row = (blockIdx.x * blockDim.x + threadIdx.x) >> 5;
    const int lane = threadIdx.x & 31;
    if (row >= NTOK) return;

    float4 xv[4];
    const float4* xr = reinterpret_cast<const float4*>(x + (size_t)row * KDIM);
    #pragma unroll
    for (int j = 0; j < 4; ++j) xv[j] = xr[lane + j * 32];

    float bd = 3.4e38f;
    int bi = NCODES;
    #pragma unroll
    for (int c = 0; c < NCAND; ++c) {
        int idx = g_cand[row * NCAND + c];
        const float4* er = reinterpret_cast<const float4*>(cb + (size_t)idx * KDIM);
        float s = 0.f;
        #pragma unroll
        for (int j = 0; j < 4; ++j) {
            float4 e = er[lane + j * 32];
            s += xv[j].x * e.x + xv[j].y * e.y + xv[j].z * e.z + xv[j].w * e.w;
        }
        #pragma unroll
        for (int o = 16; o > 0; o >>= 1) s += __shfl_xor_sync(0xffffffffu, s, o);
        float d = fmaf(-2.f, s, d_esq[idx]);
        if (d < bd || (d == bd && idx < bi)) { bd = d; bi = idx; }
    }

    const float4* vr = reinterpret_cast<const float4*>(values + (size_t)bi * KDIM);
    float4* orow = reinterpret_cast<float4*>(out + (size_t)row * KDIM);
    #pragma unroll
    for (int j = 0; j < 4; ++j) orow[lane + j * 32] = vr[lane + j * 32];
}

// ---------------------------------------------------------------------------
extern "C" void kernel_launch(void* const* d_in, const int* in_sizes, int n_in,
                              void* d_out, int out_size) {
    const float* x      = (const float*)d_in[0];   // [16384, 512]
    const float* cb     = (const float*)d_in[1];   // [8192, 512]
    const float* values = (const float*)d_in[2];   // [8192, 512]
    float* out = (float*)d_out;

    cudaFuncSetAttribute(vq_main,
                         cudaFuncAttributeMaxDynamicSharedMemorySize, SMEM_TOTAL);

    esq_kernel<<<NCODES / 8, 256>>>(cb);
    esq2_kernel<<<(NCODES / 2) / 256, 256>>>();
    conv_kernel<<<(NTOK * KDIM / 4) / 256, 256>>>(x, NTOK * KDIM / 4, 0);
    conv_kernel<<<(NCODES * KDIM / 4) / 256, 256>>>(cb, NCODES * KDIM / 4, 1);
    vq_main<<<NTOK / BM, NTHREADS, SMEM_TOTAL>>>();
    fixup_gather<<<(NTOK * 32) / 256, 256>>>(x, cb, values, out);
}

// round 17
// speedup vs baseline: 19.7598x; 1.0754x over previous
#include <cuda_runtime.h>
#include <cuda_bf16.h>
#include <cstdint>

// ============================================================================
// DiscreteKeyValueBottleneck — int8 mma.sync (m16n8k32), negated codebook +
// esq-preloaded accumulators, register-double-buffered fragment pipeline,
// packed-int top-3/top-8 selection + exact fp32 fixup + fused gather.
// ============================================================================

#define KDIM     512
#define NCODES   8192
#define NTOK     16384
#define BM       128
#define BN       128
#define NTILES   (NCODES / BN)       // 64
#define NTHREADS 512
#define NCAND    8

#define XS_BYTES   (BM * KDIM)       // 65536
#define TILE_BYTES (BN * KDIM)       // 65536
#define SMEM_TOTAL (XS_BYTES + 2 * TILE_BYTES)  // 196608

#define QSCALE   (4.0f / 127.0f)
#define QINV     (127.0f / 4.0f)
#define EBIAS    400000

__device__ int8_t g_x8[NTOK * KDIM];
__device__ int8_t g_e8[NCODES * KDIM];        // NEGATED quantized codebook
__device__ float  d_esq[NCODES];
__device__ int    g_esqi[NCODES];
__device__ int4   g_esqi2[NCODES / 2];        // {e0,e1,e0,e1} per code pair
__device__ int    g_cand[NTOK * NCAND];

// ---------------------------------------------------------------------------
__device__ __forceinline__ uint32_t smem_u32(const void* p) {
    uint32_t a;
    asm("{ .reg .u64 t; cvta.to.shared.u64 t, %1; cvt.u32.u64 %0, t; }"
        : "=r"(a) : "l"(p));
    return a;
}
__device__ __forceinline__ void cp16(uint32_t dst, const void* src) {
    asm volatile("cp.async.cg.shared.global [%0], [%1], 16;"
                 :: "r"(dst), "l"(src) : "memory");
}
#define CP_COMMIT() asm volatile("cp.async.commit_group;" ::: "memory")

__device__ __forceinline__ void ldsm4(uint32_t* r, uint32_t addr) {
    asm volatile("ldmatrix.sync.aligned.m8n8.x4.shared.b16 {%0,%1,%2,%3}, [%4];"
                 : "=r"(r[0]), "=r"(r[1]), "=r"(r[2]), "=r"(r[3]) : "r"(addr));
}
__device__ __forceinline__ void imma16832(int* d, const uint32_t* a,
                                          const uint32_t* b) {
    asm volatile(
        "mma.sync.aligned.m16n8k32.row.col.s32.s8.s8.s32 "
        "{%0,%1,%2,%3}, {%4,%5,%6,%7}, {%8,%9}, {%0,%1,%2,%3};"
        : "+r"(d[0]), "+r"(d[1]), "+r"(d[2]), "+r"(d[3])
        : "r"(a[0]), "r"(a[1]), "r"(a[2]), "r"(a[3]), "r"(b[0]), "r"(b[1]));
}

// ---------------------------------------------------------------------------
// Pre-pass kernels
// ---------------------------------------------------------------------------
__global__ void esq_kernel(const float* __restrict__ cb) {
    int warp = (blockIdx.x * blockDim.x + threadIdx.x) >> 5;
    int lane = threadIdx.x & 31;
    if (warp >= NCODES) return;
    const float4* row = reinterpret_cast<const float4*>(cb + (size_t)warp * KDIM);
    float s = 0.f;
    #pragma unroll
    for (int i = 0; i < KDIM / 4 / 32; ++i) {
        float4 v = row[lane + i * 32];
        s += v.x * v.x + v.y * v.y + v.z * v.z + v.w * v.w;
    }
    #pragma unroll
    for (int o = 16; o > 0; o >>= 1) s += __shfl_xor_sync(0xffffffffu, s, o);
    if (lane == 0) {
        d_esq[warp] = s;
        g_esqi[warp] = __float2int_rn(s / (2.0f * QSCALE * QSCALE)) + EBIAS;
    }
}

__global__ void esq2_kernel() {
    int i = blockIdx.x * blockDim.x + threadIdx.x;
    if (i >= NCODES / 2) return;
    int a = g_esqi[2 * i], b = g_esqi[2 * i + 1];
    g_esqi2[i] = make_int4(a, b, a, b);
}

__device__ __forceinline__ int qv(float v) {
    return __float2int_rn(fminf(fmaxf(v * QINV, -127.f), 127.f));
}
__global__ void conv_kernel(const float* __restrict__ src, int n4, int which) {
    int i = blockIdx.x * blockDim.x + threadIdx.x;
    if (i >= n4) return;
    int8_t* dst = which ? g_e8 : g_x8;
    float4 v = reinterpret_cast<const float4*>(src)[i];
    int q0 = qv(v.x), q1 = qv(v.y), q2 = qv(v.z), q3 = qv(v.w);
    if (which) { q0 = -q0; q1 = -q1; q2 = -q2; q3 = -q3; }
    uint32_t p = (uint32_t)(q0 & 0xff) | ((uint32_t)(q1 & 0xff) << 8) |
                 ((uint32_t)(q2 & 0xff) << 16) | ((uint32_t)(q3 & 0xff) << 24);
    reinterpret_cast<uint32_t*>(dst)[i] = p;
}

// ---------------------------------------------------------------------------
// Main kernel
// ---------------------------------------------------------------------------
extern __shared__ __align__(1024) char smem[];

__device__ __forceinline__ void load_tile(uint32_t dst, int nt, int tid) {
    const int8_t* src = g_e8 + (size_t)(nt * BN) * KDIM;
    #pragma unroll
    for (int i = 0; i < (BN * KDIM / 16) / NTHREADS; ++i) {  // 8
        int idx = tid + i * NTHREADS;
        int c = idx >> 5, sg = idx & 31;
        cp16(dst + c * 512 + ((sg * 16) ^ ((c & 7) << 4)),
             src + (size_t)c * KDIM + sg * 16);
    }
}

// packed-int top-3 insertion (sorted ascending td[rs][0..2])
#define INS3P(rs, v)                                                         \
    do {                                                                     \
        if ((v) < td[rs][2]) {                                               \
            td[rs][2] = (v);                                                 \
            if (td[rs][2] < td[rs][1]) {                                     \
                int _t = td[rs][1]; td[rs][1] = td[rs][2]; td[rs][2] = _t;   \
                if (td[rs][1] < td[rs][0]) {                                 \
                    _t = td[rs][0]; td[rs][0] = td[rs][1]; td[rs][1] = _t;   \
                }                                                            \
            }                                                                \
        }                                                                    \
    } while (0)

#define PACKV(d, code) ((((d) << 10) & 0xFFFFE000) | (code))

__global__ __launch_bounds__(NTHREADS, 1) void vq_main() {
    const int tid = threadIdx.x, lane = tid & 31, wid = tid >> 5;
    const int row0 = blockIdx.x * BM;
    const uint32_t xs_u = smem_u32(smem);
    const uint32_t st_u = xs_u + XS_BYTES;

    // ---- resident x tile ----
    #pragma unroll 4
    for (int i = 0; i < (BM * KDIM / 16) / NTHREADS; ++i) {
        int idx = tid + i * NTHREADS;
        int r = idx >> 5, sg = idx & 31;
        cp16(xs_u + r * 512 + ((sg * 16) ^ ((r & 7) << 4)),
             g_x8 + (size_t)(row0 + r) * KDIM + sg * 16);
    }
    load_tile(st_u, 0, tid);
    CP_COMMIT();

    const int rowg = wid >> 2, colg = wid & 3;
    const int mr = rowg * 32, nc = colg * 32;

    uint32_t aX[4][2], bX[4][2];
    #pragma unroll
    for (int rg = 0; rg < 2; ++rg) {
        int r = mr + rg * 16 + (lane & 15);
        uint32_t base = xs_u + r * 512 + (((lane >> 4) * 16) ^ ((r & 7) << 4));
        #pragma unroll
        for (int ks = 0; ks < 4; ++ks) aX[ks][rg] = base ^ (uint32_t)(ks << 5);
    }
    #pragma unroll
    for (int p = 0; p < 2; ++p) {
        int c = nc + p * 16 + (lane & 7) + ((lane >> 4) & 1) * 8;
        uint32_t base = (uint32_t)(c * 512) +
                        ((((lane >> 3) & 1) * 16) ^ ((c & 7) << 4));
        #pragma unroll
        for (int ks = 0; ks < 4; ++ks) bX[ks][p] = base ^ (uint32_t)(ks << 5);
    }

    int td[4][3];
    #pragma unroll
    for (int i = 0; i < 4; ++i)
        #pragma unroll
        for (int j = 0; j < 3; ++j) td[i][j] = 0x7FFFFFFF;

    int acc[2][4][4];
    uint32_t fa[2][2][4], fb[2][2][4];     // double-buffered fragments
    const int cb_lane = nc + (lane & 3) * 2;

    // fragment group loader: g = kc*4 + ks
    #define LOAD_FRAGS(buf, g, bb)                                           \
        do {                                                                 \
            const int _ks = (g) & 3;                                         \
            const uint32_t _kc = (uint32_t)(((g) >> 2) * 128);               \
            ldsm4(fa[buf][0], aX[_ks][0] + _kc);                             \
            ldsm4(fa[buf][1], aX[_ks][1] + _kc);                             \
            ldsm4(fb[buf][0], (bb) + bX[_ks][0] + _kc);                      \
            ldsm4(fb[buf][1], (bb) + bX[_ks][1] + _kc);                      \
        } while (0)

    #pragma unroll 1
    for (int nt = 0; nt < NTILES; ++nt) {
        const int code_base = nt * BN + cb_lane;

        // prefetch esqi pairs BEFORE the barrier (L2 latency overlaps wait)
        int4 ei[4];
        #pragma unroll
        for (int nf = 0; nf < 4; ++nf)
            ei[nf] = __ldg(&g_esqi2[(code_base + nf * 8) >> 1]);

        asm volatile("cp.async.wait_group 0;" ::: "memory");
        __syncthreads();
        if (nt + 1 < NTILES) {
            load_tile(st_u + ((nt + 1) & 1) * TILE_BYTES, nt + 1, tid);
            CP_COMMIT();
        }
        const uint32_t bufb = st_u + (nt & 1) * TILE_BYTES;

        // acc init = integer e_sq -> MMA accumulates distance directly
        #pragma unroll
        for (int nf = 0; nf < 4; ++nf) {
            #pragma unroll
            for (int rg = 0; rg < 2; ++rg) {
                acc[rg][nf][0] = ei[nf].x; acc[rg][nf][1] = ei[nf].y;
                acc[rg][nf][2] = ei[nf].z; acc[rg][nf][3] = ei[nf].w;
            }
        }

        // ---- software-pipelined fragment loop: load g+1 while MMA g ----
        LOAD_FRAGS(0, 0, bufb);
        #pragma unroll
        for (int g = 0; g < 16; ++g) {
            const int cur = g & 1;
            if (g < 15) LOAD_FRAGS(cur ^ 1, g + 1, bufb);
            #pragma unroll
            for (int rg = 0; rg < 2; ++rg)
                #pragma unroll
                for (int p = 0; p < 2; ++p)
                    #pragma unroll
                    for (int q = 0; q < 2; ++q)
                        imma16832(acc[rg][p * 2 + q], fa[cur][rg],
                                  fb[cur][p] + q * 2);
        }

        // ---- epilogue: acc IS the distance; pack + top-3 insert ----
        #pragma unroll
        for (int rg = 0; rg < 2; ++rg) {
            #pragma unroll
            for (int nf = 0; nf < 4; ++nf) {
                const int cg0 = code_base + nf * 8;
                int v;
                v = PACKV(acc[rg][nf][0], cg0);     INS3P(rg * 2, v);
                v = PACKV(acc[rg][nf][1], cg0 + 1); INS3P(rg * 2, v);
                v = PACKV(acc[rg][nf][2], cg0);     INS3P(rg * 2 + 1, v);
                v = PACKV(acc[rg][nf][3], cg0 + 1); INS3P(rg * 2 + 1, v);
            }
        }
    }

    // ---- per-row merge of 48 packed candidates -> global top-8 ----
    __syncthreads();
    int* md = reinterpret_cast<int*>(smem + XS_BYTES);      // [128][52] padded
    const int cid = colg * 4 + (lane & 3);
    #pragma unroll
    for (int rs = 0; rs < 4; ++rs) {
        int r = mr + (rs >> 1) * 16 + (rs & 1) * 8 + (lane >> 2);
        int o = r * 52 + cid * 3;
        #pragma unroll
        for (int j = 0; j < 3; ++j) md[o + j] = td[rs][j];
    }
    __syncthreads();
    if (tid < BM) {
        int b0 = 0x7FFFFFFF, b1 = 0x7FFFFFFF, b2 = 0x7FFFFFFF, b3 = 0x7FFFFFFF;
        int b4 = 0x7FFFFFFF, b5 = 0x7FFFFFFF, b6 = 0x7FFFFFFF, b7 = 0x7FFFFFFF;
        #pragma unroll 4
        for (int e = 0; e < 48; ++e) {
            int v = md[tid * 52 + e];
            if (v < b7) {
                b7 = v;
                if (b7 < b6) { int t=b6;b6=b7;b7=t;
                 if (b6 < b5) { t=b5;b5=b6;b6=t;
                  if (b5 < b4) { t=b4;b4=b5;b5=t;
                   if (b4 < b3) { t=b3;b3=b4;b4=t;
                    if (b3 < b2) { t=b2;b2=b3;b3=t;
                     if (b2 < b1) { t=b1;b1=b2;b2=t;
                      if (b1 < b0) { t=b0;b0=b1;b1=t; }}}}}}}
            }
        }
        int r = row0 + tid;
        g_cand[r * NCAND + 0] = b0 & 8191; g_cand[r * NCAND + 1] = b1 & 8191;
        g_cand[r * NCAND + 2] = b2 & 8191; g_cand[r * NCAND + 3] = b3 & 8191;
        g_cand[r * NCAND + 4] = b4 & 8191; g_cand[r * NCAND + 5] = b5 & 8191;
        g_cand[r * NCAND + 6] = b6 & 8191; g_cand[r * NCAND + 7] = b7 & 8191;
    }
}

// ---------------------------------------------------------------------------
// Fixup (exact fp32 rescore of NCAND candidates) fused with gather.
// ---------------------------------------------------------------------------
__global__ void fixup_gather(const float* __restrict__ x,
                             const float* __restrict__ cb,
                             const float* __restrict__ values,
                             float* __restrict__ out) {
    const int row = (blockIdx.x * blockDim.x + threadIdx.x) >> 5;
    const int lane = threadIdx.x & 31;
    if (row >= NTOK) return;

    float4 xv[4];
    const float4* xr = reinterpret_cast<const float4*>(x + (size_t)row * KDIM);
    #pragma unroll
    for (int j = 0; j < 4; ++j) xv[j] = xr[lane + j * 32];

    float bd = 3.4e38f;
    int bi = NCODES;
    #pragma unroll
    for (int c = 0; c < NCAND; ++c) {
        int idx = g_cand[row * NCAND + c];
        const float4* er = reinterpret_cast<const float4*>(cb + (size_t)idx * KDIM);
        float s = 0.f;
        #pragma unroll
        for (int j = 0; j < 4; ++j) {
            float4 e = er[lane + j * 32];
            s += xv[j].x * e.x + xv[j].y * e.y + xv[j].z * e.z + xv[j].w * e.w;
        }
        #pragma unroll
        for (int o = 16; o > 0; o >>= 1) s += __shfl_xor_sync(0xffffffffu, s, o);
        float d = fmaf(-2.f, s, d_esq[idx]);
        if (d < bd || (d == bd && idx < bi)) { bd = d; bi = idx; }
    }

    const float4* vr = reinterpret_cast<const float4*>(values + (size_t)bi * KDIM);
    float4* orow = reinterpret_cast<float4*>(out + (size_t)row * KDIM);
    #pragma unroll
    for (int j = 0; j < 4; ++j) orow[lane + j * 32] = vr[lane + j * 32];
}

// ---------------------------------------------------------------------------
extern "C" void kernel_launch(void* const* d_in, const int* in_sizes, int n_in,
                              void* d_out, int out_size) {
    const float* x      = (const float*)d_in[0];
    const float* cb     = (const float*)d_in[1];
    const float* values = (const float*)d_in[2];
    float* out = (float*)d_out;

    cudaFuncSetAttribute(vq_main,
                         cudaFuncAttributeMaxDynamicSharedMemorySize, SMEM_TOTAL);

    esq_kernel<<<NCODES / 8, 256>>>(cb);
    esq2_kernel<<<(NCODES / 2) / 256, 256>>>();
    conv_kernel<<<(NTOK * KDIM / 4) / 256, 256>>>(x, NTOK * KDIM / 4, 0);
    conv_kernel<<<(NCODES * KDIM / 4) / 256, 256>>>(cb, NCODES * KDIM / 4, 1);
    vq_main<<<NTOK / BM, NTHREADS, SMEM_TOTAL>>>();
    fixup_gather<<<(NTOK * 32) / 256, 256>>>(x, cb, values, out);
}